// round 1
// baseline (speedup 1.0000x reference)
#include <cuda_runtime.h>
#include <cuda_bf16.h>
#include <math.h>

// ---------------------------------------------------------------------------
// Problem constants (B=2, H=W=64, C=256, nh=4, hd=64, k=7)
// ---------------------------------------------------------------------------
#define NTOK   8192          // B*H*W
#define CDIM   256
#define HDIM   64
#define NHEAD  4
#define KS     7
#define KK     49            // KS*KS
#define QKVN   768           // 3*C
#define FFN    512           // 2*C

// ---------------------------------------------------------------------------
// Scratch buffers (__device__ globals; no allocation allowed)
// ---------------------------------------------------------------------------
__device__ float g_h   [NTOK * CDIM];   // rmsnorm1 + rope output
__device__ float g_qkv [NTOK * QKVN];   // qkv projection
__device__ float g_attn[NTOK * CDIM];   // attention output (pre-proj)
__device__ float g_x1  [NTOK * CDIM];   // x + attn_proj  (residual 1)
__device__ float g_n2  [NTOK * CDIM];   // rmsnorm2 output
__device__ float g_ffh [NTOK * FFN];    // ff1 output (gate|value)
__device__ float g_g   [NTOK * CDIM];   // gelu(gate)*value

// ---------------------------------------------------------------------------
// RMSNorm (+ optional RoPE2D). One block per token, 128 threads, each thread
// owns one (even,odd) pair of channels so rope rotation is local.
// ---------------------------------------------------------------------------
__global__ void rmsnorm_rope_kernel(const float* __restrict__ x,
                                    const float* __restrict__ w,
                                    float* __restrict__ out,
                                    int do_rope)
{
    const int t = blockIdx.x;            // token
    const int i = threadIdx.x;           // pair index 0..127
    const float2* xin = reinterpret_cast<const float2*>(x + (size_t)t * CDIM);
    float2 v = xin[i];

    float ss = v.x * v.x + v.y * v.y;
    #pragma unroll
    for (int off = 16; off; off >>= 1)
        ss += __shfl_xor_sync(0xffffffffu, ss, off);

    __shared__ float red[4];
    if ((i & 31) == 0) red[i >> 5] = ss;
    __syncthreads();
    const float total = red[0] + red[1] + red[2] + red[3];
    const float r = rsqrtf(total * (1.0f / CDIM) + 1e-6f);

    const float2 wv = reinterpret_cast<const float2*>(w)[i];
    float a = v.x * r * wv.x;
    float b = v.y * r * wv.y;

    if (do_rope) {
        const int yy = (t >> 6) & 63;
        const int xx = t & 63;
        const int j  = i & 63;                       // freq index 0..63
        const float pos = (i < 64) ? (float)yy : (float)xx;
        const float inv = powf(10000.0f, -(float)j * (1.0f / 64.0f));
        float c, s;
        sincosf(pos * inv, &s, &c);                  // NOTE: sincosf(x, sin, cos)
        const float na = a * c - b * s;
        const float nb = a * s + b * c;
        a = na; b = nb;
    }

    reinterpret_cast<float2*>(out + (size_t)t * CDIM)[i] = make_float2(a, b);
}

// ---------------------------------------------------------------------------
// Generic tiled SGEMM: C[M,N] = A[M,K] @ B[K,N]  (+ bias) (+ residual)
// BM=BN=64, BK=16, 256 threads, 4x4 per thread, float4 smem paths.
// mode: 0 = plain, 1 = +bias, 2 = +bias +residual
// Requires M%64==0, N%64==0, K%16==0 (true for all four GEMMs here).
// ---------------------------------------------------------------------------
__global__ __launch_bounds__(256)
void gemm_kernel(const float* __restrict__ A,
                 const float* __restrict__ B,
                 const float* __restrict__ bias,
                 const float* __restrict__ residual,
                 float* __restrict__ C,
                 int M, int N, int K, int mode)
{
    __shared__ __align__(16) float As[16][68];   // [k][m], padded row stride 68
    __shared__ __align__(16) float Bs[16][64];   // [k][n]

    const int tid = threadIdx.x;
    const int tx  = tid & 15;       // 0..15 (N direction)
    const int ty  = tid >> 4;       // 0..15 (M direction)
    const int bm  = blockIdx.y * 64;
    const int bn  = blockIdx.x * 64;

    float acc[4][4] = {};

    // A-tile loader mapping: one float4 per thread
    const int ar  = tid >> 2;       // 0..63  (row within tile)
    const int ac4 = tid & 3;        // 0..3   (float4 col within 16)
    // B-tile loader mapping
    const int br  = tid >> 4;       // 0..15  (k row)
    const int bc4 = tid & 15;       // 0..15  (float4 col within 64)

    for (int k0 = 0; k0 < K; k0 += 16) {
        float4 av = *reinterpret_cast<const float4*>(
            &A[(size_t)(bm + ar) * K + k0 + ac4 * 4]);
        float4 bv = *reinterpret_cast<const float4*>(
            &B[(size_t)(k0 + br) * N + bn + bc4 * 4]);

        As[ac4 * 4 + 0][ar] = av.x;
        As[ac4 * 4 + 1][ar] = av.y;
        As[ac4 * 4 + 2][ar] = av.z;
        As[ac4 * 4 + 3][ar] = av.w;
        *reinterpret_cast<float4*>(&Bs[br][bc4 * 4]) = bv;
        __syncthreads();

        #pragma unroll
        for (int kk = 0; kk < 16; kk++) {
            const float4 a = *reinterpret_cast<const float4*>(&As[kk][ty * 4]);
            const float4 b = *reinterpret_cast<const float4*>(&Bs[kk][tx * 4]);
            const float ax[4] = {a.x, a.y, a.z, a.w};
            const float bxv[4] = {b.x, b.y, b.z, b.w};
            #pragma unroll
            for (int ii = 0; ii < 4; ii++)
                #pragma unroll
                for (int jj = 0; jj < 4; jj++)
                    acc[ii][jj] = fmaf(ax[ii], bxv[jj], acc[ii][jj]);
        }
        __syncthreads();
    }

    const int row0 = bm + ty * 4;
    const int col0 = bn + tx * 4;
    #pragma unroll
    for (int ii = 0; ii < 4; ii++) {
        const size_t rbase = (size_t)(row0 + ii) * N + col0;
        float4 o = make_float4(acc[ii][0], acc[ii][1], acc[ii][2], acc[ii][3]);
        if (mode >= 1) {
            o.x += bias[col0 + 0]; o.y += bias[col0 + 1];
            o.z += bias[col0 + 2]; o.w += bias[col0 + 3];
        }
        if (mode == 2) {
            const float4 rres = *reinterpret_cast<const float4*>(&residual[rbase]);
            o.x += rres.x; o.y += rres.y; o.z += rres.z; o.w += rres.w;
        }
        *reinterpret_cast<float4*>(&C[rbase]) = o;
    }
}

// ---------------------------------------------------------------------------
// Neighborhood attention: one warp per (token, head). 49 neighbors always
// fully in-bounds (window start clamped). Lane owns dims {lane, lane+32}.
// ---------------------------------------------------------------------------
__global__ __launch_bounds__(128)
void attn_kernel(const float* __restrict__ qkv, float* __restrict__ out)
{
    const int t    = blockIdx.x;
    const int head = threadIdx.x >> 5;
    const int lane = threadIdx.x & 31;

    const int b  = t >> 12;
    const int yy = (t >> 6) & 63;
    const int xx = t & 63;
    const int y0 = min(max(yy - 3, 0), 64 - KS);
    const int x0 = min(max(xx - 3, 0), 64 - KS);

    const float* q = qkv + (size_t)t * QKVN + head * HDIM;
    const float q0 = q[lane];
    const float q1 = q[lane + 32];

    float logits[KK];
    #pragma unroll
    for (int j = 0; j < KK; j++) {
        const int ny = y0 + j / KS;
        const int nx = x0 + j % KS;
        const int nt = (b << 12) + (ny << 6) + nx;
        const float* kp = qkv + (size_t)nt * QKVN + CDIM + head * HDIM;
        float s = q0 * kp[lane] + q1 * kp[lane + 32];
        #pragma unroll
        for (int off = 16; off; off >>= 1)
            s += __shfl_xor_sync(0xffffffffu, s, off);
        logits[j] = s * 0.125f;   // 1/sqrt(64)
    }

    float m = -1e30f;
    #pragma unroll
    for (int j = 0; j < KK; j++) m = fmaxf(m, logits[j]);

    float denom = 0.0f;
    #pragma unroll
    for (int j = 0; j < KK; j++) {
        logits[j] = expf(logits[j] - m);
        denom += logits[j];
    }

    float acc0 = 0.0f, acc1 = 0.0f;
    #pragma unroll
    for (int j = 0; j < KK; j++) {
        const int ny = y0 + j / KS;
        const int nx = x0 + j % KS;
        const int nt = (b << 12) + (ny << 6) + nx;
        const float* vp = qkv + (size_t)nt * QKVN + 2 * CDIM + head * HDIM;
        acc0 = fmaf(logits[j], vp[lane], acc0);
        acc1 = fmaf(logits[j], vp[lane + 32], acc1);
    }
    const float inv = 1.0f / denom;
    out[(size_t)t * CDIM + head * HDIM + lane]      = acc0 * inv;
    out[(size_t)t * CDIM + head * HDIM + lane + 32] = acc1 * inv;
}

// ---------------------------------------------------------------------------
// GeGLU elementwise: g = gelu_exact(gate) * value
// ---------------------------------------------------------------------------
__global__ void geglu_kernel(const float* __restrict__ ffh, float* __restrict__ g)
{
    const int idx = blockIdx.x * blockDim.x + threadIdx.x;   // over NTOK*CDIM
    const int row = idx >> 8;
    const int col = idx & 255;
    const float gate = ffh[(size_t)row * FFN + col];
    const float val  = ffh[(size_t)row * FFN + CDIM + col];
    const float ge = 0.5f * gate * (1.0f + erff(gate * 0.70710678118654752f));
    g[idx] = ge * val;
}

// ---------------------------------------------------------------------------
// Launch
// ---------------------------------------------------------------------------
extern "C" void kernel_launch(void* const* d_in, const int* in_sizes, int n_in,
                              void* d_out, int out_size)
{
    const float* x       = (const float*)d_in[0];
    const float* norm1_w = (const float*)d_in[1];
    const float* norm2_w = (const float*)d_in[2];
    const float* w_qkv   = (const float*)d_in[3];
    const float* w_proj  = (const float*)d_in[4];
    const float* b_proj  = (const float*)d_in[5];
    const float* ff1_w   = (const float*)d_in[6];
    const float* ff1_b   = (const float*)d_in[7];
    const float* ff2_w   = (const float*)d_in[8];
    const float* ff2_b   = (const float*)d_in[9];
    float* out = (float*)d_out;

    float *p_h, *p_qkv, *p_attn, *p_x1, *p_n2, *p_ffh, *p_g;
    cudaGetSymbolAddress((void**)&p_h,    g_h);
    cudaGetSymbolAddress((void**)&p_qkv,  g_qkv);
    cudaGetSymbolAddress((void**)&p_attn, g_attn);
    cudaGetSymbolAddress((void**)&p_x1,   g_x1);
    cudaGetSymbolAddress((void**)&p_n2,   g_n2);
    cudaGetSymbolAddress((void**)&p_ffh,  g_ffh);
    cudaGetSymbolAddress((void**)&p_g,    g_g);

    // 1. h = rope2d(rmsnorm(x, norm1_w))
    rmsnorm_rope_kernel<<<NTOK, 128>>>(x, norm1_w, p_h, 1);

    // 2. qkv = h @ w_qkv            [8192,768]
    gemm_kernel<<<dim3(QKVN / 64, NTOK / 64), 256>>>(
        p_h, w_qkv, nullptr, nullptr, p_qkv, NTOK, QKVN, CDIM, 0);

    // 3. neighborhood attention     [8192,256]
    attn_kernel<<<NTOK, 128>>>(p_qkv, p_attn);

    // 4. x1 = x + attn @ w_proj + b_proj
    gemm_kernel<<<dim3(CDIM / 64, NTOK / 64), 256>>>(
        p_attn, w_proj, b_proj, x, p_x1, NTOK, CDIM, CDIM, 2);

    // 5. n2 = rmsnorm(x1, norm2_w)
    rmsnorm_rope_kernel<<<NTOK, 128>>>(p_x1, norm2_w, p_n2, 0);

    // 6. ffh = n2 @ ff1_w + ff1_b   [8192,512]
    gemm_kernel<<<dim3(FFN / 64, NTOK / 64), 256>>>(
        p_n2, ff1_w, ff1_b, nullptr, p_ffh, NTOK, FFN, CDIM, 1);

    // 7. g = gelu(gate) * value     [8192,256]
    geglu_kernel<<<(NTOK * CDIM) / 256, 256>>>(p_ffh, p_g);

    // 8. out = x1 + g @ ff2_w + ff2_b
    gemm_kernel<<<dim3(CDIM / 64, NTOK / 64), 256>>>(
        p_g, ff2_w, ff2_b, p_x1, out, NTOK, CDIM, CDIM, 2);
}

// round 3
// speedup vs baseline: 2.2786x; 2.2786x over previous
#include <cuda_runtime.h>
#include <cuda_bf16.h>
#include <math.h>
#include <stdint.h>

// ---------------------------------------------------------------------------
// Problem constants (B=2, H=W=64, C=256, nh=4, hd=64, k=7)
// ---------------------------------------------------------------------------
#define NTOK   8192
#define CDIM   256
#define GK     256      // K dim of every GEMM
#define QKVN   768
#define FFN    512
#define KS     7
#define KK     49

// ---------------------------------------------------------------------------
// Scratch (__device__ globals; allocation forbidden)
// ---------------------------------------------------------------------------
__device__ __nv_bfloat16 g_h   [NTOK * CDIM];   // rmsnorm1+rope
__device__ __nv_bfloat16 g_qkv [NTOK * QKVN];   // qkv (bf16, read by attention)
__device__ __nv_bfloat16 g_attn[NTOK * CDIM];   // attention out
__device__ float         g_x1  [NTOK * CDIM];   // residual 1 (fp32)
__device__ __nv_bfloat16 g_n2  [NTOK * CDIM];   // rmsnorm2
__device__ float         g_ffh [NTOK * FFN];    // ff1 out (fp32)
__device__ __nv_bfloat16 g_g   [NTOK * CDIM];   // geglu out
// transposed bf16 weights: wT[n*GK + k] = w[k*N + n]
__device__ __nv_bfloat16 g_wqkvT[QKVN * GK];
__device__ __nv_bfloat16 g_wprojT[CDIM * GK];
__device__ __nv_bfloat16 g_ff1T [FFN  * GK];
__device__ __nv_bfloat16 g_ff2T [CDIM * GK];

// ---------------------------------------------------------------------------
// Weight convert + transpose: w[K x N] fp32 -> wT[N x GK] bf16
// ---------------------------------------------------------------------------
__global__ void transpose_bf16_kernel(const float* __restrict__ w,
                                      __nv_bfloat16* __restrict__ wt, int N)
{
    __shared__ float t[32][33];
    const int n0 = blockIdx.x * 32, k0 = blockIdx.y * 32;
    const int tx = threadIdx.x, ty = threadIdx.y;   // 32 x 8
    #pragma unroll
    for (int i = 0; i < 32; i += 8)
        t[ty + i][tx] = w[(size_t)(k0 + ty + i) * N + n0 + tx];
    __syncthreads();
    #pragma unroll
    for (int i = 0; i < 32; i += 8)
        wt[(size_t)(n0 + ty + i) * GK + k0 + tx] = __float2bfloat16(t[tx][ty + i]);
}

// ---------------------------------------------------------------------------
// RMSNorm (+ optional RoPE2D), fp32 in, bf16 out. One block per token.
// ---------------------------------------------------------------------------
__global__ void rmsnorm_rope_kernel(const float* __restrict__ x,
                                    const float* __restrict__ w,
                                    __nv_bfloat16* __restrict__ out,
                                    int do_rope)
{
    const int t = blockIdx.x;
    const int i = threadIdx.x;
    float2 v = reinterpret_cast<const float2*>(x + (size_t)t * CDIM)[i];

    float ss = v.x * v.x + v.y * v.y;
    #pragma unroll
    for (int off = 16; off; off >>= 1)
        ss += __shfl_xor_sync(0xffffffffu, ss, off);
    __shared__ float red[4];
    if ((i & 31) == 0) red[i >> 5] = ss;
    __syncthreads();
    const float r = rsqrtf((red[0] + red[1] + red[2] + red[3]) * (1.0f / CDIM) + 1e-6f);

    const float2 wv = reinterpret_cast<const float2*>(w)[i];
    float a = v.x * r * wv.x;
    float b = v.y * r * wv.y;

    if (do_rope) {
        const int yy = (t >> 6) & 63;
        const int xx = t & 63;
        const int j  = i & 63;
        const float pos = (i < 64) ? (float)yy : (float)xx;
        const float inv = powf(10000.0f, -(float)j * (1.0f / 64.0f));
        float c, s;
        sincosf(pos * inv, &s, &c);
        const float na = a * c - b * s;
        const float nb = a * s + b * c;
        a = na; b = nb;
    }
    reinterpret_cast<__nv_bfloat162*>(out + (size_t)t * CDIM)[i] =
        __floats2bfloat162_rn(a, b);
}

// ---------------------------------------------------------------------------
// mma.sync bf16 GEMM:  C[8192, N] = A[8192, 256] @ Bt[N, 256]^T
// CTA 128x128, full K resident in smem (64KB + 64KB), 8 warps (2M x 4N),
// warp tile 64x32, mma.m16n8k16 fp32 accum.
// smem layout per tile: 4 column-blocks (k/64) of [row(128) x 128B], XOR-swizzled.
// mode: 0 = bf16 out, 1 = fp32 +bias, 2 = fp32 +bias +residual
// ---------------------------------------------------------------------------
#define SM_B_OFF 65536
#define SM_SIZE  131072

__device__ __forceinline__ uint32_t smem_u32(const void* p) {
    uint32_t a;
    asm("{ .reg .u64 t; cvta.to.shared.u64 t, %1; cvt.u32.u64 %0, t; }"
        : "=r"(a) : "l"(p));
    return a;
}
#define LDMATRIX_X4(r0, r1, r2, r3, a) \
    asm volatile("ldmatrix.sync.aligned.m8n8.x4.shared.b16 {%0,%1,%2,%3}, [%4];" \
                 : "=r"(r0), "=r"(r1), "=r"(r2), "=r"(r3) : "r"(a))
#define MMA_BF16(d, a, b) \
    asm volatile("mma.sync.aligned.m16n8k16.row.col.f32.bf16.bf16.f32 " \
                 "{%0,%1,%2,%3}, {%4,%5,%6,%7}, {%8,%9}, {%0,%1,%2,%3};" \
                 : "+f"((d)[0]), "+f"((d)[1]), "+f"((d)[2]), "+f"((d)[3]) \
                 : "r"((a)[0]), "r"((a)[1]), "r"((a)[2]), "r"((a)[3]), \
                   "r"((b)[0]), "r"((b)[1]))

__global__ __launch_bounds__(256, 1)
void gemm_mma_kernel(const __nv_bfloat16* __restrict__ A,
                     const __nv_bfloat16* __restrict__ Bt,
                     const float* __restrict__ bias,
                     const float* __restrict__ residual,
                     float* __restrict__ C,
                     __nv_bfloat16* __restrict__ Cb,
                     int N, int mode)
{
    extern __shared__ __align__(1024) char smem[];
    const uint32_t sbA = smem_u32(smem);
    const uint32_t sbB = sbA + SM_B_OFF;
    const int tid  = threadIdx.x;
    const int wid  = tid >> 5;
    const int lane = tid & 31;
    const int bm   = blockIdx.y * 128;
    const int bn   = blockIdx.x * 128;
    const int wm   = wid & 1;        // M half (64 rows)
    const int wn   = wid >> 1;       // N quarter (32 cols)

    // ---- load A,B tiles (128 rows x 256 bf16 = 512B/row) into swizzled smem ----
    // row layout: 4 col-blocks (k-chunk of 64 bf16 = 128B) x 128 rows x 128B
    {
        const uint32_t cb  = (uint32_t)(lane >> 3) * 16384u;
        const uint32_t inb = (uint32_t)(lane & 7) * 16u;
        #pragma unroll 4
        for (int it = 0; it < 16; it++) {
            const int row = it * 8 + wid;
            uint32_t boff = cb + (uint32_t)row * 128u + inb;
            boff ^= (boff >> 3) & 0x70;
            uint4 va = reinterpret_cast<const uint4*>(A  + (size_t)(bm + row) * GK)[lane];
            uint4 vb = reinterpret_cast<const uint4*>(Bt + (size_t)(bn + row) * GK)[lane];
            *reinterpret_cast<uint4*>(smem + boff)            = va;
            *reinterpret_cast<uint4*>(smem + SM_B_OFF + boff) = vb;
        }
    }
    __syncthreads();

    float acc[4][4][4] = {};
    const int mtx = lane >> 3;       // ldmatrix matrix id 0..3
    const int l7  = lane & 7;

    #pragma unroll
    for (int s = 0; s < 16; s++) {                 // k16 steps over K=256
        const uint32_t cbase  = (uint32_t)(s >> 2) * 16384u;
        const int      chunk0 = (s & 3) * 2;       // 16B chunk base within 128B row

        // A fragments: 4 m16 tiles
        uint32_t af[4][4];
        #pragma unroll
        for (int mt = 0; mt < 4; mt++) {
            const int row   = wm * 64 + mt * 16 + (mtx & 1) * 8 + l7;
            const int chunk = chunk0 + (mtx >> 1);
            uint32_t off = cbase + (uint32_t)row * 128u + (uint32_t)chunk * 16u;
            off ^= (off >> 3) & 0x70;
            LDMATRIX_X4(af[mt][0], af[mt][1], af[mt][2], af[mt][3], sbA + off);
        }
        // B fragments: 4 n8 tiles (two per ldmatrix.x4)
        uint32_t bf[4][2];
        #pragma unroll
        for (int pair = 0; pair < 2; pair++) {
            const int nrow  = wn * 32 + pair * 16 + (mtx >> 1) * 8 + l7;
            const int chunk = chunk0 + (mtx & 1);
            uint32_t off = cbase + (uint32_t)nrow * 128u + (uint32_t)chunk * 16u;
            off ^= (off >> 3) & 0x70;
            LDMATRIX_X4(bf[pair * 2][0], bf[pair * 2][1],
                        bf[pair * 2 + 1][0], bf[pair * 2 + 1][1], sbB + off);
        }
        #pragma unroll
        for (int mt = 0; mt < 4; mt++)
            #pragma unroll
            for (int nt = 0; nt < 4; nt++)
                MMA_BF16(acc[mt][nt], af[mt], bf[nt]);
    }

    // ---- epilogue ----
    const int rbase = bm + wm * 64 + (lane >> 2);
    const int cbase = bn + wn * 32 + (lane & 3) * 2;
    #pragma unroll
    for (int mt = 0; mt < 4; mt++) {
        #pragma unroll
        for (int half = 0; half < 2; half++) {     // d0d1 (row) / d2d3 (row+8)
            const int row = rbase + mt * 16 + half * 8;
            #pragma unroll
            for (int nt = 0; nt < 4; nt++) {
                const int col = cbase + nt * 8;
                float ox = acc[mt][nt][half * 2];
                float oy = acc[mt][nt][half * 2 + 1];
                const size_t idx = (size_t)row * N + col;
                if (mode == 0) {
                    *reinterpret_cast<__nv_bfloat162*>(&Cb[idx]) =
                        __floats2bfloat162_rn(ox, oy);
                } else {
                    ox += bias[col];
                    oy += bias[col + 1];
                    if (mode == 2) {
                        const float2 rr = *reinterpret_cast<const float2*>(&residual[idx]);
                        ox += rr.x; oy += rr.y;
                    }
                    *reinterpret_cast<float2*>(&C[idx]) = make_float2(ox, oy);
                }
            }
        }
    }
}

// ---------------------------------------------------------------------------
// Neighborhood attention (bf16 qkv in, bf16 out). One warp per (token, head).
// Lane owns dims {2*lane, 2*lane+1}: one bf162 load per neighbor per tensor.
// ---------------------------------------------------------------------------
__global__ __launch_bounds__(128)
void attn_kernel(const __nv_bfloat16* __restrict__ qkv, __nv_bfloat16* __restrict__ out)
{
    const int t    = blockIdx.x;
    const int head = threadIdx.x >> 5;
    const int lane = threadIdx.x & 31;

    const int b  = t >> 12;
    const int yy = (t >> 6) & 63;
    const int xx = t & 63;
    const int y0 = min(max(yy - 3, 0), 64 - KS);
    const int x0 = min(max(xx - 3, 0), 64 - KS);

    const float2 qf = __bfloat1622float2(
        reinterpret_cast<const __nv_bfloat162*>(qkv + (size_t)t * QKVN + head * 64)[lane]);

    float logits[KK];
    #pragma unroll
    for (int j = 0; j < KK; j++) {
        const int nt = (b << 12) + ((y0 + j / KS) << 6) + (x0 + j % KS);
        const float2 kf = __bfloat1622float2(
            reinterpret_cast<const __nv_bfloat162*>(
                qkv + (size_t)nt * QKVN + CDIM + head * 64)[lane]);
        float s = qf.x * kf.x + qf.y * kf.y;
        #pragma unroll
        for (int off = 16; off; off >>= 1)
            s += __shfl_xor_sync(0xffffffffu, s, off);
        logits[j] = s * 0.125f;
    }
    float m = -1e30f;
    #pragma unroll
    for (int j = 0; j < KK; j++) m = fmaxf(m, logits[j]);
    float denom = 0.0f;
    #pragma unroll
    for (int j = 0; j < KK; j++) { logits[j] = expf(logits[j] - m); denom += logits[j]; }

    float ax = 0.0f, ay = 0.0f;
    #pragma unroll
    for (int j = 0; j < KK; j++) {
        const int nt = (b << 12) + ((y0 + j / KS) << 6) + (x0 + j % KS);
        const float2 vf = __bfloat1622float2(
            reinterpret_cast<const __nv_bfloat162*>(
                qkv + (size_t)nt * QKVN + 2 * CDIM + head * 64)[lane]);
        ax = fmaf(logits[j], vf.x, ax);
        ay = fmaf(logits[j], vf.y, ay);
    }
    const float inv = 1.0f / denom;
    reinterpret_cast<__nv_bfloat162*>(out + (size_t)t * CDIM + head * 64)[lane] =
        __floats2bfloat162_rn(ax * inv, ay * inv);
}

// ---------------------------------------------------------------------------
// GeGLU: g = gelu_exact(gate) * value   (fp32 in, bf16 out)
// ---------------------------------------------------------------------------
__global__ void geglu_kernel(const float* __restrict__ ffh, __nv_bfloat16* __restrict__ g)
{
    const int idx = blockIdx.x * blockDim.x + threadIdx.x;
    const int row = idx >> 8;
    const int col = idx & 255;
    const float gate = ffh[(size_t)row * FFN + col];
    const float val  = ffh[(size_t)row * FFN + CDIM + col];
    const float ge = 0.5f * gate * (1.0f + erff(gate * 0.70710678118654752f));
    g[idx] = __float2bfloat16(ge * val);
}

// ---------------------------------------------------------------------------
// Launch
// ---------------------------------------------------------------------------
extern "C" void kernel_launch(void* const* d_in, const int* in_sizes, int n_in,
                              void* d_out, int out_size)
{
    const float* x       = (const float*)d_in[0];
    const float* norm1_w = (const float*)d_in[1];
    const float* norm2_w = (const float*)d_in[2];
    const float* w_qkv   = (const float*)d_in[3];
    const float* w_proj  = (const float*)d_in[4];
    const float* b_proj  = (const float*)d_in[5];
    const float* ff1_w   = (const float*)d_in[6];
    const float* ff1_b   = (const float*)d_in[7];
    const float* ff2_w   = (const float*)d_in[8];
    const float* ff2_b   = (const float*)d_in[9];
    float* out = (float*)d_out;

    __nv_bfloat16 *p_h, *p_qkv, *p_attn, *p_n2, *p_g;
    __nv_bfloat16 *p_wqkvT, *p_wprojT, *p_ff1T, *p_ff2T;
    float *p_x1, *p_ffh;
    cudaGetSymbolAddress((void**)&p_h,      g_h);
    cudaGetSymbolAddress((void**)&p_qkv,    g_qkv);
    cudaGetSymbolAddress((void**)&p_attn,   g_attn);
    cudaGetSymbolAddress((void**)&p_x1,     g_x1);
    cudaGetSymbolAddress((void**)&p_n2,     g_n2);
    cudaGetSymbolAddress((void**)&p_ffh,    g_ffh);
    cudaGetSymbolAddress((void**)&p_g,      g_g);
    cudaGetSymbolAddress((void**)&p_wqkvT,  g_wqkvT);
    cudaGetSymbolAddress((void**)&p_wprojT, g_wprojT);
    cudaGetSymbolAddress((void**)&p_ff1T,   g_ff1T);
    cudaGetSymbolAddress((void**)&p_ff2T,   g_ff2T);

    cudaFuncSetAttribute(gemm_mma_kernel,
                         cudaFuncAttributeMaxDynamicSharedMemorySize, SM_SIZE);

    // 0. weight convert + transpose (fp32 [K,N] -> bf16 [N,K])
    transpose_bf16_kernel<<<dim3(QKVN / 32, 8), dim3(32, 8)>>>(w_qkv,  p_wqkvT,  QKVN);
    transpose_bf16_kernel<<<dim3(CDIM / 32, 8), dim3(32, 8)>>>(w_proj, p_wprojT, CDIM);
    transpose_bf16_kernel<<<dim3(FFN  / 32, 8), dim3(32, 8)>>>(ff1_w,  p_ff1T,   FFN);
    transpose_bf16_kernel<<<dim3(CDIM / 32, 8), dim3(32, 8)>>>(ff2_w,  p_ff2T,   CDIM);

    // 1. h = rope2d(rmsnorm(x)) -> bf16
    rmsnorm_rope_kernel<<<NTOK, 128>>>(x, norm1_w, p_h, 1);

    // 2. qkv = h @ w_qkv -> bf16
    gemm_mma_kernel<<<dim3(QKVN / 128, NTOK / 128), 256, SM_SIZE>>>(
        p_h, p_wqkvT, nullptr, nullptr, nullptr, p_qkv, QKVN, 0);

    // 3. neighborhood attention -> bf16
    attn_kernel<<<NTOK, 128>>>(p_qkv, p_attn);

    // 4. x1 = x + attn @ w_proj + b_proj   (fp32)
    gemm_mma_kernel<<<dim3(CDIM / 128, NTOK / 128), 256, SM_SIZE>>>(
        p_attn, p_wprojT, b_proj, x, p_x1, nullptr, CDIM, 2);

    // 5. n2 = rmsnorm(x1) -> bf16
    rmsnorm_rope_kernel<<<NTOK, 128>>>(p_x1, norm2_w, p_n2, 0);

    // 6. ffh = n2 @ ff1_w + ff1_b   (fp32)
    gemm_mma_kernel<<<dim3(FFN / 128, NTOK / 128), 256, SM_SIZE>>>(
        p_n2, p_ff1T, ff1_b, nullptr, p_ffh, nullptr, FFN, 1);

    // 7. g = gelu(gate) * value -> bf16
    geglu_kernel<<<(NTOK * CDIM) / 256, 256>>>(p_ffh, p_g);

    // 8. out = x1 + g @ ff2_w + ff2_b   (fp32)
    gemm_mma_kernel<<<dim3(CDIM / 128, NTOK / 128), 256, SM_SIZE>>>(
        p_g, p_ff2T, ff2_b, p_x1, out, nullptr, CDIM, 2);
}

// round 4
// speedup vs baseline: 3.3930x; 1.4890x over previous
#include <cuda_runtime.h>
#include <cuda_bf16.h>
#include <math.h>
#include <stdint.h>

// ---------------------------------------------------------------------------
// Problem constants (B=2, H=W=64, C=256, nh=4, hd=64, k=7)
// ---------------------------------------------------------------------------
#define NTOK   8192
#define CDIM   256
#define GK     256
#define QKVN   768
#define FFN    512
#define KS     7
#define KK     49

// ---------------------------------------------------------------------------
// Scratch (__device__ globals; allocation forbidden)
// ---------------------------------------------------------------------------
__device__ __nv_bfloat16 g_h   [NTOK * CDIM];
__device__ __nv_bfloat16 g_qkv [NTOK * QKVN];
__device__ __nv_bfloat16 g_attn[NTOK * CDIM];
__device__ float         g_x1  [NTOK * CDIM];
__device__ __nv_bfloat16 g_n2  [NTOK * CDIM];
__device__ float         g_ffh [NTOK * FFN];
__device__ __nv_bfloat16 g_g   [NTOK * CDIM];
__device__ __nv_bfloat16 g_wqkvT[QKVN * GK];
__device__ __nv_bfloat16 g_wprojT[CDIM * GK];
__device__ __nv_bfloat16 g_ff1T [FFN  * GK];
__device__ __nv_bfloat16 g_ff2T [CDIM * GK];

// ---------------------------------------------------------------------------
// PTX helpers
// ---------------------------------------------------------------------------
__device__ __forceinline__ uint32_t smem_u32(const void* p) {
    uint32_t a;
    asm("{ .reg .u64 t; cvta.to.shared.u64 t, %1; cvt.u32.u64 %0, t; }"
        : "=r"(a) : "l"(p));
    return a;
}
#define LDMATRIX_X4(r0, r1, r2, r3, a) \
    asm volatile("ldmatrix.sync.aligned.m8n8.x4.shared.b16 {%0,%1,%2,%3}, [%4];" \
                 : "=r"(r0), "=r"(r1), "=r"(r2), "=r"(r3) : "r"(a))
#define MMA_BF16(d, a, b) \
    asm volatile("mma.sync.aligned.m16n8k16.row.col.f32.bf16.bf16.f32 " \
                 "{%0,%1,%2,%3}, {%4,%5,%6,%7}, {%8,%9}, {%0,%1,%2,%3};" \
                 : "+f"((d)[0]), "+f"((d)[1]), "+f"((d)[2]), "+f"((d)[3]) \
                 : "r"((a)[0]), "r"((a)[1]), "r"((a)[2]), "r"((a)[3]), \
                   "r"((b)[0]), "r"((b)[1]))
#define CP_ASYNC16(dst, src) \
    asm volatile("cp.async.cg.shared.global [%0], [%1], 16;" :: "r"(dst), "l"(src))
#define CP_COMMIT() asm volatile("cp.async.commit_group;" ::: "memory")
#define CP_WAIT(n)  asm volatile("cp.async.wait_group %0;" :: "n"(n) : "memory")

// ---------------------------------------------------------------------------
// Fused weight convert+transpose: all 4 weights in ONE launch.
// w[K x N] fp32 -> wT[N x GK] bf16.  grid.x = 24+8+16+8 = 56 n-blocks, grid.y = 8
// ---------------------------------------------------------------------------
__global__ void transpose_all_kernel(const float* __restrict__ w0, __nv_bfloat16* __restrict__ o0,
                                     const float* __restrict__ w1, __nv_bfloat16* __restrict__ o1,
                                     const float* __restrict__ w2, __nv_bfloat16* __restrict__ o2,
                                     const float* __restrict__ w3, __nv_bfloat16* __restrict__ o3)
{
    const float* w; __nv_bfloat16* o; int N, nb;
    const int bx = blockIdx.x;
    if      (bx < 24) { w = w0; o = o0; N = QKVN; nb = bx;      }
    else if (bx < 32) { w = w1; o = o1; N = CDIM; nb = bx - 24; }
    else if (bx < 48) { w = w2; o = o2; N = FFN;  nb = bx - 32; }
    else              { w = w3; o = o3; N = CDIM; nb = bx - 48; }

    __shared__ float t[32][33];
    const int n0 = nb * 32, k0 = blockIdx.y * 32;
    const int tx = threadIdx.x, ty = threadIdx.y;   // 32 x 8
    #pragma unroll
    for (int i = 0; i < 32; i += 8)
        t[ty + i][tx] = w[(size_t)(k0 + ty + i) * N + n0 + tx];
    __syncthreads();
    #pragma unroll
    for (int i = 0; i < 32; i += 8)
        o[(size_t)(n0 + ty + i) * GK + k0 + tx] = __float2bfloat16(t[tx][ty + i]);
}

// ---------------------------------------------------------------------------
// RMSNorm (+ optional RoPE2D), fp32 in, bf16 out.
// ---------------------------------------------------------------------------
__global__ void rmsnorm_rope_kernel(const float* __restrict__ x,
                                    const float* __restrict__ w,
                                    __nv_bfloat16* __restrict__ out,
                                    int do_rope)
{
    const int t = blockIdx.x;
    const int i = threadIdx.x;
    float2 v = reinterpret_cast<const float2*>(x + (size_t)t * CDIM)[i];

    float ss = v.x * v.x + v.y * v.y;
    #pragma unroll
    for (int off = 16; off; off >>= 1)
        ss += __shfl_xor_sync(0xffffffffu, ss, off);
    __shared__ float red[4];
    if ((i & 31) == 0) red[i >> 5] = ss;
    __syncthreads();
    const float r = rsqrtf((red[0] + red[1] + red[2] + red[3]) * (1.0f / CDIM) + 1e-6f);

    const float2 wv = reinterpret_cast<const float2*>(w)[i];
    float a = v.x * r * wv.x;
    float b = v.y * r * wv.y;

    if (do_rope) {
        const int yy = (t >> 6) & 63;
        const int xx = t & 63;
        const int j  = i & 63;
        const float pos = (i < 64) ? (float)yy : (float)xx;
        const float inv = exp2f((float)j * (-13.28771237954945f / 64.0f)); // log2(10000)
        float c, s;
        sincosf(pos * inv, &s, &c);
        const float na = a * c - b * s;
        const float nb = a * s + b * c;
        a = na; b = nb;
    }
    reinterpret_cast<__nv_bfloat162*>(out + (size_t)t * CDIM)[i] =
        __floats2bfloat162_rn(a, b);
}

// ---------------------------------------------------------------------------
// mma.sync bf16 GEMM with cp.async pipelined tile load.
// CTA 128x128, K=256 resident as 4 chunks of 64 (16KB per operand per chunk).
// 8 warps (2M x 4N), warp tile 64x32, mma.m16n8k16 fp32 accum.
// mode: 0 = bf16 out, 1 = fp32 +bias, 2 = fp32 +bias +residual
// ---------------------------------------------------------------------------
#define SM_B_OFF 65536
#define SM_SIZE  131072

__global__ __launch_bounds__(256, 1)
void gemm_mma_kernel(const __nv_bfloat16* __restrict__ A,
                     const __nv_bfloat16* __restrict__ Bt,
                     const float* __restrict__ bias,
                     const float* __restrict__ residual,
                     float* __restrict__ C,
                     __nv_bfloat16* __restrict__ Cb,
                     int N, int mode)
{
    extern __shared__ __align__(1024) char smem[];
    const uint32_t sbA = smem_u32(smem);
    const uint32_t sbB = sbA + SM_B_OFF;
    const int tid  = threadIdx.x;
    const int wid  = tid >> 5;
    const int lane = tid & 31;
    const int bm   = blockIdx.y * 128;
    const int bn   = blockIdx.x * 128;
    const int wm   = wid & 1;
    const int wn   = wid >> 1;

    // ---- prefetch all 4 K-chunks via cp.async (one commit group per chunk) ----
    #pragma unroll
    for (int kc = 0; kc < 4; kc++) {
        #pragma unroll
        for (int it = 0; it < 4; it++) {
            const int idx = it * 256 + tid;            // 0..1023 16B-chunks
            const int row = idx >> 3;
            uint32_t off = (uint32_t)kc * 16384u + (uint32_t)row * 128u
                         + (uint32_t)(idx & 7) * 16u;
            off ^= (off >> 3) & 0x70;
            const __nv_bfloat16* ga = A  + (size_t)(bm + row) * GK + kc * 64 + (idx & 7) * 8;
            const __nv_bfloat16* gb = Bt + (size_t)(bn + row) * GK + kc * 64 + (idx & 7) * 8;
            CP_ASYNC16(sbA + off, ga);
            CP_ASYNC16(sbB + off, gb);
        }
        CP_COMMIT();
    }

    float acc[4][4][4] = {};
    const int mtx = lane >> 3;
    const int l7  = lane & 7;

    #pragma unroll
    for (int kc = 0; kc < 4; kc++) {
        if      (kc == 0) CP_WAIT(3);
        else if (kc == 1) CP_WAIT(2);
        else if (kc == 2) CP_WAIT(1);
        else              CP_WAIT(0);
        __syncthreads();

        #pragma unroll
        for (int s16 = 0; s16 < 4; s16++) {
            const uint32_t cbase  = (uint32_t)kc * 16384u;
            const int      chunk0 = s16 * 2;

            uint32_t af[4][4];
            #pragma unroll
            for (int mt = 0; mt < 4; mt++) {
                const int row   = wm * 64 + mt * 16 + (mtx & 1) * 8 + l7;
                const int chunk = chunk0 + (mtx >> 1);
                uint32_t off = cbase + (uint32_t)row * 128u + (uint32_t)chunk * 16u;
                off ^= (off >> 3) & 0x70;
                LDMATRIX_X4(af[mt][0], af[mt][1], af[mt][2], af[mt][3], sbA + off);
            }
            uint32_t bf[4][2];
            #pragma unroll
            for (int pair = 0; pair < 2; pair++) {
                const int nrow  = wn * 32 + pair * 16 + (mtx >> 1) * 8 + l7;
                const int chunk = chunk0 + (mtx & 1);
                uint32_t off = cbase + (uint32_t)nrow * 128u + (uint32_t)chunk * 16u;
                off ^= (off >> 3) & 0x70;
                LDMATRIX_X4(bf[pair * 2][0], bf[pair * 2][1],
                            bf[pair * 2 + 1][0], bf[pair * 2 + 1][1], sbB + off);
            }
            #pragma unroll
            for (int mt = 0; mt < 4; mt++)
                #pragma unroll
                for (int nt = 0; nt < 4; nt++)
                    MMA_BF16(acc[mt][nt], af[mt], bf[nt]);
        }
    }

    // ---- epilogue ----
    const int rbase = bm + wm * 64 + (lane >> 2);
    const int cbase = bn + wn * 32 + (lane & 3) * 2;
    #pragma unroll
    for (int mt = 0; mt < 4; mt++) {
        #pragma unroll
        for (int half = 0; half < 2; half++) {
            const int row = rbase + mt * 16 + half * 8;
            #pragma unroll
            for (int nt = 0; nt < 4; nt++) {
                const int col = cbase + nt * 8;
                float ox = acc[mt][nt][half * 2];
                float oy = acc[mt][nt][half * 2 + 1];
                const size_t idx = (size_t)row * N + col;
                if (mode == 0) {
                    *reinterpret_cast<__nv_bfloat162*>(&Cb[idx]) =
                        __floats2bfloat162_rn(ox, oy);
                } else {
                    ox += bias[col];
                    oy += bias[col + 1];
                    if (mode == 2) {
                        const float2 rr = *reinterpret_cast<const float2*>(&residual[idx]);
                        ox += rr.x; oy += rr.y;
                    }
                    *reinterpret_cast<float2*>(&C[idx]) = make_float2(ox, oy);
                }
            }
        }
    }
}

// ---------------------------------------------------------------------------
// Neighborhood attention, group-parallel scheme.
// One warp per (token, head). Lane = (g, c): g = neighbor-group 0..3,
// c = dim-chunk 0..7 (8 bf16 dims = one uint4). 13 passes x 4 neighbors.
// ---------------------------------------------------------------------------
__global__ __launch_bounds__(128)
void attn_kernel(const __nv_bfloat16* __restrict__ qkv, __nv_bfloat16* __restrict__ out)
{
    const int t    = blockIdx.x;
    const int head = threadIdx.x >> 5;
    const int lane = threadIdx.x & 31;
    const int g    = lane >> 3;
    const int c    = lane & 7;

    const int b  = t >> 12;
    const int yy = (t >> 6) & 63;
    const int xx = t & 63;
    const int y0 = min(max(yy - 3, 0), 64 - KS);
    const int x0 = min(max(xx - 3, 0), 64 - KS);

    __shared__ float sexp[4][52];

    // q dims [c*8, c*8+8)
    const uint4 q4 = *reinterpret_cast<const uint4*>(
        qkv + (size_t)t * QKVN + head * 64 + c * 8);
    const float2 q0 = __bfloat1622float2(((const __nv_bfloat162*)&q4)[0]);
    const float2 q1 = __bfloat1622float2(((const __nv_bfloat162*)&q4)[1]);
    const float2 q2 = __bfloat1622float2(((const __nv_bfloat162*)&q4)[2]);
    const float2 q3 = __bfloat1622float2(((const __nv_bfloat162*)&q4)[3]);

    // ---- logits ----
    #pragma unroll
    for (int p = 0; p < 13; p++) {
        const int j = p * 4 + g;
        float s = 0.0f;
        if (j < KK) {
            const int nt = (b << 12) + ((y0 + j / KS) << 6) + (x0 + j % KS);
            const uint4 k4 = *reinterpret_cast<const uint4*>(
                qkv + (size_t)nt * QKVN + CDIM + head * 64 + c * 8);
            const float2 k0 = __bfloat1622float2(((const __nv_bfloat162*)&k4)[0]);
            const float2 k1 = __bfloat1622float2(((const __nv_bfloat162*)&k4)[1]);
            const float2 k2 = __bfloat1622float2(((const __nv_bfloat162*)&k4)[2]);
            const float2 k3 = __bfloat1622float2(((const __nv_bfloat162*)&k4)[3]);
            s = q0.x * k0.x + q0.y * k0.y + q1.x * k1.x + q1.y * k1.y
              + q2.x * k2.x + q2.y * k2.y + q3.x * k3.x + q3.y * k3.y;
        }
        s += __shfl_xor_sync(0xffffffffu, s, 1);
        s += __shfl_xor_sync(0xffffffffu, s, 2);
        s += __shfl_xor_sync(0xffffffffu, s, 4);
        if (c == 0 && j < KK) sexp[head][j] = s * 0.125f;
    }
    __syncwarp();

    // ---- softmax (unnormalized exp stored back) ----
    const float v1 = (lane < KK) ? sexp[head][lane] : -1e30f;
    const float v2 = (lane + 32 < KK) ? sexp[head][lane + 32] : -1e30f;
    float m = fmaxf(v1, v2);
    #pragma unroll
    for (int off = 16; off; off >>= 1)
        m = fmaxf(m, __shfl_xor_sync(0xffffffffu, m, off));
    const float e1 = (lane < KK) ? expf(v1 - m) : 0.0f;
    const float e2 = (lane + 32 < KK) ? expf(v2 - m) : 0.0f;
    float denom = e1 + e2;
    #pragma unroll
    for (int off = 16; off; off >>= 1)
        denom += __shfl_xor_sync(0xffffffffu, denom, off);
    if (lane < KK) sexp[head][lane] = e1;
    if (lane + 32 < KK) sexp[head][lane + 32] = e2;
    __syncwarp();

    // ---- V accumulation ----
    float acc[8] = {};
    #pragma unroll
    for (int p = 0; p < 13; p++) {
        const int j = p * 4 + g;
        if (j < KK) {
            const float w = sexp[head][j];
            const int nt = (b << 12) + ((y0 + j / KS) << 6) + (x0 + j % KS);
            const uint4 v4 = *reinterpret_cast<const uint4*>(
                qkv + (size_t)nt * QKVN + 2 * CDIM + head * 64 + c * 8);
            #pragma unroll
            for (int h2 = 0; h2 < 4; h2++) {
                const float2 vf = __bfloat1622float2(((const __nv_bfloat162*)&v4)[h2]);
                acc[h2 * 2]     = fmaf(w, vf.x, acc[h2 * 2]);
                acc[h2 * 2 + 1] = fmaf(w, vf.y, acc[h2 * 2 + 1]);
            }
        }
    }
    #pragma unroll
    for (int i = 0; i < 8; i++) {
        acc[i] += __shfl_xor_sync(0xffffffffu, acc[i], 8);
        acc[i] += __shfl_xor_sync(0xffffffffu, acc[i], 16);
    }
    if (g == 0) {
        const float inv = 1.0f / denom;
        uint4 o;
        ((__nv_bfloat162*)&o)[0] = __floats2bfloat162_rn(acc[0] * inv, acc[1] * inv);
        ((__nv_bfloat162*)&o)[1] = __floats2bfloat162_rn(acc[2] * inv, acc[3] * inv);
        ((__nv_bfloat162*)&o)[2] = __floats2bfloat162_rn(acc[4] * inv, acc[5] * inv);
        ((__nv_bfloat162*)&o)[3] = __floats2bfloat162_rn(acc[6] * inv, acc[7] * inv);
        *reinterpret_cast<uint4*>(out + (size_t)t * CDIM + head * 64 + c * 8) = o;
    }
}

// ---------------------------------------------------------------------------
// GeGLU: g = gelu_exact(gate) * value   (fp32 in, bf16 out)
// ---------------------------------------------------------------------------
__global__ void geglu_kernel(const float* __restrict__ ffh, __nv_bfloat16* __restrict__ g)
{
    const int idx = blockIdx.x * blockDim.x + threadIdx.x;
    const int row = idx >> 8;
    const int col = idx & 255;
    const float gate = ffh[(size_t)row * FFN + col];
    const float val  = ffh[(size_t)row * FFN + CDIM + col];
    const float ge = 0.5f * gate * (1.0f + erff(gate * 0.70710678118654752f));
    g[idx] = __float2bfloat16(ge * val);
}

// ---------------------------------------------------------------------------
// Launch
// ---------------------------------------------------------------------------
extern "C" void kernel_launch(void* const* d_in, const int* in_sizes, int n_in,
                              void* d_out, int out_size)
{
    const float* x       = (const float*)d_in[0];
    const float* norm1_w = (const float*)d_in[1];
    const float* norm2_w = (const float*)d_in[2];
    const float* w_qkv   = (const float*)d_in[3];
    const float* w_proj  = (const float*)d_in[4];
    const float* b_proj  = (const float*)d_in[5];
    const float* ff1_w   = (const float*)d_in[6];
    const float* ff1_b   = (const float*)d_in[7];
    const float* ff2_w   = (const float*)d_in[8];
    const float* ff2_b   = (const float*)d_in[9];
    float* out = (float*)d_out;

    __nv_bfloat16 *p_h, *p_qkv, *p_attn, *p_n2, *p_g;
    __nv_bfloat16 *p_wqkvT, *p_wprojT, *p_ff1T, *p_ff2T;
    float *p_x1, *p_ffh;
    cudaGetSymbolAddress((void**)&p_h,      g_h);
    cudaGetSymbolAddress((void**)&p_qkv,    g_qkv);
    cudaGetSymbolAddress((void**)&p_attn,   g_attn);
    cudaGetSymbolAddress((void**)&p_x1,     g_x1);
    cudaGetSymbolAddress((void**)&p_n2,     g_n2);
    cudaGetSymbolAddress((void**)&p_ffh,    g_ffh);
    cudaGetSymbolAddress((void**)&p_g,      g_g);
    cudaGetSymbolAddress((void**)&p_wqkvT,  g_wqkvT);
    cudaGetSymbolAddress((void**)&p_wprojT, g_wprojT);
    cudaGetSymbolAddress((void**)&p_ff1T,   g_ff1T);
    cudaGetSymbolAddress((void**)&p_ff2T,   g_ff2T);

    cudaFuncSetAttribute(gemm_mma_kernel,
                         cudaFuncAttributeMaxDynamicSharedMemorySize, SM_SIZE);

    // 0. all weight transposes in one launch
    transpose_all_kernel<<<dim3(56, 8), dim3(32, 8)>>>(
        w_qkv, p_wqkvT, w_proj, p_wprojT, ff1_w, p_ff1T, ff2_w, p_ff2T);

    // 1. h = rope2d(rmsnorm(x)) -> bf16
    rmsnorm_rope_kernel<<<NTOK, 128>>>(x, norm1_w, p_h, 1);

    // 2. qkv = h @ w_qkv -> bf16
    gemm_mma_kernel<<<dim3(QKVN / 128, NTOK / 128), 256, SM_SIZE>>>(
        p_h, p_wqkvT, nullptr, nullptr, nullptr, p_qkv, QKVN, 0);

    // 3. neighborhood attention -> bf16
    attn_kernel<<<NTOK, 128>>>(p_qkv, p_attn);

    // 4. x1 = x + attn @ w_proj + b_proj   (fp32)
    gemm_mma_kernel<<<dim3(CDIM / 128, NTOK / 128), 256, SM_SIZE>>>(
        p_attn, p_wprojT, b_proj, x, p_x1, nullptr, CDIM, 2);

    // 5. n2 = rmsnorm(x1) -> bf16
    rmsnorm_rope_kernel<<<NTOK, 128>>>(p_x1, norm2_w, p_n2, 0);

    // 6. ffh = n2 @ ff1_w + ff1_b   (fp32)
    gemm_mma_kernel<<<dim3(FFN / 128, NTOK / 128), 256, SM_SIZE>>>(
        p_n2, p_ff1T, ff1_b, nullptr, p_ffh, nullptr, FFN, 1);

    // 7. g = gelu(gate) * value -> bf16
    geglu_kernel<<<(NTOK * CDIM) / 256, 256>>>(p_ffh, p_g);

    // 8. out = x1 + g @ ff2_w + ff2_b   (fp32)
    gemm_mma_kernel<<<dim3(CDIM / 128, NTOK / 128), 256, SM_SIZE>>>(
        p_g, p_ff2T, ff2_b, p_x1, out, nullptr, CDIM, 2);
}

// round 5
// speedup vs baseline: 4.0092x; 1.1816x over previous
#include <cuda_runtime.h>
#include <cuda_bf16.h>
#include <math.h>
#include <stdint.h>

// ---------------------------------------------------------------------------
// Problem constants (B=2, H=W=64, C=256, nh=4, hd=64, k=7)
// ---------------------------------------------------------------------------
#define NTOK   8192
#define CDIM   256
#define GK     256
#define QKVN   768
#define FFN    512
#define KS     7
#define KK     49

// ---------------------------------------------------------------------------
// Scratch (__device__ globals; allocation forbidden)
// ---------------------------------------------------------------------------
__device__ __nv_bfloat16 g_h   [NTOK * CDIM];
__device__ __nv_bfloat16 g_qkv [NTOK * QKVN];
__device__ __nv_bfloat16 g_attn[NTOK * CDIM];
__device__ float         g_x1  [NTOK * CDIM];
__device__ __nv_bfloat16 g_n2  [NTOK * CDIM];
__device__ float         g_ffh [NTOK * FFN];
__device__ __nv_bfloat16 g_g   [NTOK * CDIM];
__device__ __nv_bfloat16 g_wqkvT[QKVN * GK];
__device__ __nv_bfloat16 g_wprojT[CDIM * GK];
__device__ __nv_bfloat16 g_ff1T [FFN  * GK];
__device__ __nv_bfloat16 g_ff2T [CDIM * GK];

// ---------------------------------------------------------------------------
// PTX helpers
// ---------------------------------------------------------------------------
__device__ __forceinline__ uint32_t smem_u32(const void* p) {
    uint32_t a;
    asm("{ .reg .u64 t; cvta.to.shared.u64 t, %1; cvt.u32.u64 %0, t; }"
        : "=r"(a) : "l"(p));
    return a;
}
#define LDMATRIX_X4(r0, r1, r2, r3, a) \
    asm volatile("ldmatrix.sync.aligned.m8n8.x4.shared.b16 {%0,%1,%2,%3}, [%4];" \
                 : "=r"(r0), "=r"(r1), "=r"(r2), "=r"(r3) : "r"(a))
#define LDMATRIX_X4_TRANS(r0, r1, r2, r3, a) \
    asm volatile("ldmatrix.sync.aligned.m8n8.x4.trans.shared.b16 {%0,%1,%2,%3}, [%4];" \
                 : "=r"(r0), "=r"(r1), "=r"(r2), "=r"(r3) : "r"(a))
#define MMA_BF16(d, a, b) \
    asm volatile("mma.sync.aligned.m16n8k16.row.col.f32.bf16.bf16.f32 " \
                 "{%0,%1,%2,%3}, {%4,%5,%6,%7}, {%8,%9}, {%0,%1,%2,%3};" \
                 : "+f"((d)[0]), "+f"((d)[1]), "+f"((d)[2]), "+f"((d)[3]) \
                 : "r"((a)[0]), "r"((a)[1]), "r"((a)[2]), "r"((a)[3]), \
                   "r"((b)[0]), "r"((b)[1]))
#define CP_ASYNC16(dst, src) \
    asm volatile("cp.async.cg.shared.global [%0], [%1], 16;" :: "r"(dst), "l"(src))
#define CP_COMMIT() asm volatile("cp.async.commit_group;" ::: "memory")
#define CP_WAIT(n)  asm volatile("cp.async.wait_group %0;" :: "n"(n) : "memory")

__device__ __forceinline__ uint32_t swz(uint32_t off) { return off ^ ((off >> 3) & 0x70); }

// ---------------------------------------------------------------------------
// Fused weight convert+transpose (one launch for all 4 weights)
// ---------------------------------------------------------------------------
__global__ void transpose_all_kernel(const float* __restrict__ w0, __nv_bfloat16* __restrict__ o0,
                                     const float* __restrict__ w1, __nv_bfloat16* __restrict__ o1,
                                     const float* __restrict__ w2, __nv_bfloat16* __restrict__ o2,
                                     const float* __restrict__ w3, __nv_bfloat16* __restrict__ o3)
{
    const float* w; __nv_bfloat16* o; int N, nb;
    const int bx = blockIdx.x;
    if      (bx < 24) { w = w0; o = o0; N = QKVN; nb = bx;      }
    else if (bx < 32) { w = w1; o = o1; N = CDIM; nb = bx - 24; }
    else if (bx < 48) { w = w2; o = o2; N = FFN;  nb = bx - 32; }
    else              { w = w3; o = o3; N = CDIM; nb = bx - 48; }

    __shared__ float t[32][33];
    const int n0 = nb * 32, k0 = blockIdx.y * 32;
    const int tx = threadIdx.x, ty = threadIdx.y;
    #pragma unroll
    for (int i = 0; i < 32; i += 8)
        t[ty + i][tx] = w[(size_t)(k0 + ty + i) * N + n0 + tx];
    __syncthreads();
    #pragma unroll
    for (int i = 0; i < 32; i += 8)
        o[(size_t)(n0 + ty + i) * GK + k0 + tx] = __float2bfloat16(t[tx][ty + i]);
}

// ---------------------------------------------------------------------------
// RMSNorm (+ optional RoPE2D), fp32 in, bf16 out.
// ---------------------------------------------------------------------------
__global__ void rmsnorm_rope_kernel(const float* __restrict__ x,
                                    const float* __restrict__ w,
                                    __nv_bfloat16* __restrict__ out,
                                    int do_rope)
{
    const int t = blockIdx.x;
    const int i = threadIdx.x;
    float2 v = reinterpret_cast<const float2*>(x + (size_t)t * CDIM)[i];

    float ss = v.x * v.x + v.y * v.y;
    #pragma unroll
    for (int off = 16; off; off >>= 1)
        ss += __shfl_xor_sync(0xffffffffu, ss, off);
    __shared__ float red[4];
    if ((i & 31) == 0) red[i >> 5] = ss;
    __syncthreads();
    const float r = rsqrtf((red[0] + red[1] + red[2] + red[3]) * (1.0f / CDIM) + 1e-6f);

    const float2 wv = reinterpret_cast<const float2*>(w)[i];
    float a = v.x * r * wv.x;
    float b = v.y * r * wv.y;

    if (do_rope) {
        const int yy = (t >> 6) & 63;
        const int xx = t & 63;
        const int j  = i & 63;
        const float pos = (i < 64) ? (float)yy : (float)xx;
        const float inv = exp2f((float)j * (-13.28771237954945f / 64.0f));
        float c, s;
        sincosf(pos * inv, &s, &c);
        const float na = a * c - b * s;
        const float nb = a * s + b * c;
        a = na; b = nb;
    }
    reinterpret_cast<__nv_bfloat162*>(out + (size_t)t * CDIM)[i] =
        __floats2bfloat162_rn(a, b);
}

// ---------------------------------------------------------------------------
// mma.sync bf16 GEMM with cp.async pipelined tile load (unchanged from R4).
// ---------------------------------------------------------------------------
#define SM_B_OFF 65536
#define SM_SIZE  131072

__global__ __launch_bounds__(256, 1)
void gemm_mma_kernel(const __nv_bfloat16* __restrict__ A,
                     const __nv_bfloat16* __restrict__ Bt,
                     const float* __restrict__ bias,
                     const float* __restrict__ residual,
                     float* __restrict__ C,
                     __nv_bfloat16* __restrict__ Cb,
                     int N, int mode)
{
    extern __shared__ __align__(1024) char smem[];
    const uint32_t sbA = smem_u32(smem);
    const uint32_t sbB = sbA + SM_B_OFF;
    const int tid  = threadIdx.x;
    const int wid  = tid >> 5;
    const int lane = tid & 31;
    const int bm   = blockIdx.y * 128;
    const int bn   = blockIdx.x * 128;
    const int wm   = wid & 1;
    const int wn   = wid >> 1;

    #pragma unroll
    for (int kc = 0; kc < 4; kc++) {
        #pragma unroll
        for (int it = 0; it < 4; it++) {
            const int idx = it * 256 + tid;
            const int row = idx >> 3;
            uint32_t off = swz((uint32_t)kc * 16384u + (uint32_t)row * 128u
                               + (uint32_t)(idx & 7) * 16u);
            const __nv_bfloat16* ga = A  + (size_t)(bm + row) * GK + kc * 64 + (idx & 7) * 8;
            const __nv_bfloat16* gb = Bt + (size_t)(bn + row) * GK + kc * 64 + (idx & 7) * 8;
            CP_ASYNC16(sbA + off, ga);
            CP_ASYNC16(sbB + off, gb);
        }
        CP_COMMIT();
    }

    float acc[4][4][4] = {};
    const int mtx = lane >> 3;
    const int l7  = lane & 7;

    #pragma unroll
    for (int kc = 0; kc < 4; kc++) {
        if      (kc == 0) CP_WAIT(3);
        else if (kc == 1) CP_WAIT(2);
        else if (kc == 2) CP_WAIT(1);
        else              CP_WAIT(0);
        __syncthreads();

        #pragma unroll
        for (int s16 = 0; s16 < 4; s16++) {
            const uint32_t cbase  = (uint32_t)kc * 16384u;
            const int      chunk0 = s16 * 2;

            uint32_t af[4][4];
            #pragma unroll
            for (int mt = 0; mt < 4; mt++) {
                const int row   = wm * 64 + mt * 16 + (mtx & 1) * 8 + l7;
                const int chunk = chunk0 + (mtx >> 1);
                uint32_t off = swz(cbase + (uint32_t)row * 128u + (uint32_t)chunk * 16u);
                LDMATRIX_X4(af[mt][0], af[mt][1], af[mt][2], af[mt][3], sbA + off);
            }
            uint32_t bf[4][2];
            #pragma unroll
            for (int pair = 0; pair < 2; pair++) {
                const int nrow  = wn * 32 + pair * 16 + (mtx >> 1) * 8 + l7;
                const int chunk = chunk0 + (mtx & 1);
                uint32_t off = swz(cbase + (uint32_t)nrow * 128u + (uint32_t)chunk * 16u);
                LDMATRIX_X4(bf[pair * 2][0], bf[pair * 2][1],
                            bf[pair * 2 + 1][0], bf[pair * 2 + 1][1], sbB + off);
            }
            #pragma unroll
            for (int mt = 0; mt < 4; mt++)
                #pragma unroll
                for (int nt = 0; nt < 4; nt++)
                    MMA_BF16(acc[mt][nt], af[mt], bf[nt]);
        }
    }

    const int rbase = bm + wm * 64 + (lane >> 2);
    const int cbase = bn + wn * 32 + (lane & 3) * 2;
    #pragma unroll
    for (int mt = 0; mt < 4; mt++) {
        #pragma unroll
        for (int half = 0; half < 2; half++) {
            const int row = rbase + mt * 16 + half * 8;
            #pragma unroll
            for (int nt = 0; nt < 4; nt++) {
                const int col = cbase + nt * 8;
                float ox = acc[mt][nt][half * 2];
                float oy = acc[mt][nt][half * 2 + 1];
                const size_t idx = (size_t)row * N + col;
                if (mode == 0) {
                    *reinterpret_cast<__nv_bfloat162*>(&Cb[idx]) =
                        __floats2bfloat162_rn(ox, oy);
                } else {
                    ox += bias[col];
                    oy += bias[col + 1];
                    if (mode == 2) {
                        const float2 rr = *reinterpret_cast<const float2*>(&residual[idx]);
                        ox += rr.x; oy += rr.y;
                    }
                    *reinterpret_cast<float2*>(&C[idx]) = make_float2(ox, oy);
                }
            }
        }
    }
}

// ---------------------------------------------------------------------------
// Tiled tensor-core neighborhood attention.
// One CTA per (8x8 token tile, head, batch). 256 threads (8 warps).
// Phase 1: S[64,224] = Q @ K^T (mma), mask 7x7 windows, softmax -> P (bf16 smem)
// Phase 2: O[64,64]  = P @ V   (mma, V via ldmatrix.trans)
// kv slot n: r = n>>4 (14 rows), c = n&15 (cols 0..13 valid, 14..15 zero pad)
// ---------------------------------------------------------------------------
#define AT_Q    0
#define AT_K    8192
#define AT_V    36864
#define AT_P    65536
#define AT_MAX  98304
#define AT_SUM  98816
#define AT_SIZE 99328
#define NKV     224

__global__ __launch_bounds__(256)
void attn_mma_kernel(const __nv_bfloat16* __restrict__ qkv,
                     __nv_bfloat16* __restrict__ out)
{
    extern __shared__ __align__(1024) char smem[];
    const uint32_t sb = smem_u32(smem);
    float* smax = reinterpret_cast<float*>(smem + AT_MAX);   // [64][2]
    float* ssum = reinterpret_cast<float*>(smem + AT_SUM);   // [64][2]

    const int tid  = threadIdx.x;
    const int wid  = tid >> 5;
    const int lane = tid & 31;
    const int head = blockIdx.y;
    const int b    = blockIdx.z;
    const int ty0  = (blockIdx.x >> 3) * 8;
    const int tx0  = (blockIdx.x & 7) * 8;
    const int ny0  = min(max(ty0 - 3, 0), 50);
    const int nx0  = min(max(tx0 - 3, 0), 50);

    const __nv_bfloat16* base = qkv + (size_t)b * 4096 * QKVN + head * 64;

    // ---- async loads: Q (group then K, then V) ----
    #pragma unroll
    for (int i = 0; i < 2; i++) {                    // Q: 64 rows x 8 chunks
        const int idx = i * 256 + tid;
        const int m = idx >> 3, ch = idx & 7;
        const int y = ty0 + (m >> 3), x = tx0 + (m & 7);
        uint32_t off = swz((uint32_t)m * 128u + (uint32_t)ch * 16u);
        CP_ASYNC16(sb + AT_Q + off, base + (size_t)(y * 64 + x) * QKVN + ch * 8);
    }
    CP_COMMIT();
    #pragma unroll
    for (int i = 0; i < 7; i++) {                    // K: 224 rows x 8 chunks
        const int idx = i * 256 + tid;
        const int kv = idx >> 3, ch = idx & 7;
        const int r = kv >> 4, c = kv & 15;
        uint32_t off = swz((uint32_t)kv * 128u + (uint32_t)ch * 16u);
        if (c < 14)
            CP_ASYNC16(sb + AT_K + off,
                       base + (size_t)((ny0 + r) * 64 + nx0 + c) * QKVN + CDIM + ch * 8);
        else
            *reinterpret_cast<uint4*>(smem + AT_K + off) = make_uint4(0, 0, 0, 0);
    }
    CP_COMMIT();
    #pragma unroll
    for (int i = 0; i < 7; i++) {                    // V
        const int idx = i * 256 + tid;
        const int kv = idx >> 3, ch = idx & 7;
        const int r = kv >> 4, c = kv & 15;
        uint32_t off = swz((uint32_t)kv * 128u + (uint32_t)ch * 16u);
        if (c < 14)
            CP_ASYNC16(sb + AT_V + off,
                       base + (size_t)((ny0 + r) * 64 + nx0 + c) * QKVN + 2 * CDIM + ch * 8);
        else
            *reinterpret_cast<uint4*>(smem + AT_V + off) = make_uint4(0, 0, 0, 0);
    }
    CP_COMMIT();

    // ---- phase 1: S = Q @ K^T,  warp (wm, wn): rows wm*16..+16, kv wn*112..+112
    const int wm  = wid & 3;
    const int wn  = wid >> 2;
    const int mtx = lane >> 3;
    const int l7  = lane & 7;

    CP_WAIT(1);          // Q + K arrived
    __syncthreads();

    float acc[14][4] = {};
    #pragma unroll
    for (int k16 = 0; k16 < 4; k16++) {
        uint32_t af[4];
        {
            const int row   = wm * 16 + (mtx & 1) * 8 + l7;
            const int chunk = k16 * 2 + (mtx >> 1);
            LDMATRIX_X4(af[0], af[1], af[2], af[3],
                        sb + AT_Q + swz((uint32_t)row * 128u + (uint32_t)chunk * 16u));
        }
        uint32_t bf[14][2];
        #pragma unroll
        for (int pair = 0; pair < 7; pair++) {
            const int nrow  = wn * 112 + pair * 16 + (mtx >> 1) * 8 + l7;
            const int chunk = k16 * 2 + (mtx & 1);
            LDMATRIX_X4(bf[pair * 2][0], bf[pair * 2][1],
                        bf[pair * 2 + 1][0], bf[pair * 2 + 1][1],
                        sb + AT_K + swz((uint32_t)nrow * 128u + (uint32_t)chunk * 16u));
        }
        #pragma unroll
        for (int nt = 0; nt < 14; nt++)
            MMA_BF16(acc[nt], af, bf[nt]);
    }

    // ---- masks (7x7 window per token) ----
    const int row0 = wm * 16 + (lane >> 2);
    const int row1 = row0 + 8;
    const int y_a = ty0 + (row0 >> 3), x_a = tx0 + (row0 & 7);
    const int y_b = ty0 + (row1 >> 3), x_b = tx0 + (row1 & 7);
    const int rlo_a = min(max(y_a - 3, 0), 57) - ny0;
    const int clo_a = min(max(x_a - 3, 0), 57) - nx0;
    const int rlo_b = min(max(y_b - 3, 0), 57) - ny0;
    const int clo_b = min(max(x_b - 3, 0), 57) - nx0;

    uint32_t vm_a = 0, vm_b = 0;   // 28 validity bits each (t8*2 + j)
    #pragma unroll
    for (int nt = 0; nt < 14; nt++) {
        #pragma unroll
        for (int j = 0; j < 2; j++) {
            const int n = wn * 112 + nt * 8 + (lane & 3) * 2 + j;
            const int r = n >> 4, c = n & 15;
            if (c < 14 && (unsigned)(r - rlo_a) < 7u && (unsigned)(c - clo_a) < 7u)
                vm_a |= 1u << (nt * 2 + j);
            if (c < 14 && (unsigned)(r - rlo_b) < 7u && (unsigned)(c - clo_b) < 7u)
                vm_b |= 1u << (nt * 2 + j);
        }
    }

    // ---- row max ----
    float mx_a = -3e38f, mx_b = -3e38f;
    #pragma unroll
    for (int nt = 0; nt < 14; nt++) {
        #pragma unroll
        for (int j = 0; j < 2; j++) {
            if (vm_a & (1u << (nt * 2 + j))) mx_a = fmaxf(mx_a, acc[nt][j]);
            if (vm_b & (1u << (nt * 2 + j))) mx_b = fmaxf(mx_b, acc[nt][2 + j]);
        }
    }
    mx_a = fmaxf(mx_a, __shfl_xor_sync(0xffffffffu, mx_a, 1));
    mx_a = fmaxf(mx_a, __shfl_xor_sync(0xffffffffu, mx_a, 2));
    mx_b = fmaxf(mx_b, __shfl_xor_sync(0xffffffffu, mx_b, 1));
    mx_b = fmaxf(mx_b, __shfl_xor_sync(0xffffffffu, mx_b, 2));
    if ((lane & 3) == 0) {
        smax[row0 * 2 + wn] = mx_a;
        smax[row1 * 2 + wn] = mx_b;
    }
    __syncthreads();
    const float M_a = fmaxf(smax[row0 * 2], smax[row0 * 2 + 1]);
    const float M_b = fmaxf(smax[row1 * 2], smax[row1 * 2 + 1]);

    // ---- exp + row sum (P stored unnormalized) ----
    const float SC = 0.18033688011112042f;   // 0.125 * log2(e)
    float sm_a = 0.0f, sm_b = 0.0f;
    #pragma unroll
    for (int nt = 0; nt < 14; nt++) {
        #pragma unroll
        for (int j = 0; j < 2; j++) {
            float ea = (vm_a & (1u << (nt * 2 + j)))
                     ? exp2f((acc[nt][j] - M_a) * SC) : 0.0f;
            float eb = (vm_b & (1u << (nt * 2 + j)))
                     ? exp2f((acc[nt][2 + j] - M_b) * SC) : 0.0f;
            acc[nt][j] = ea; acc[nt][2 + j] = eb;
            sm_a += ea; sm_b += eb;
        }
    }
    sm_a += __shfl_xor_sync(0xffffffffu, sm_a, 1);
    sm_a += __shfl_xor_sync(0xffffffffu, sm_a, 2);
    sm_b += __shfl_xor_sync(0xffffffffu, sm_b, 1);
    sm_b += __shfl_xor_sync(0xffffffffu, sm_b, 2);
    if ((lane & 3) == 0) {
        ssum[row0 * 2 + wn] = sm_a;
        ssum[row1 * 2 + wn] = sm_b;
    }

    // ---- store P (bf16, swizzled, 4 col-blocks of 64 kv) ----
    #pragma unroll
    for (int nt = 0; nt < 14; nt++) {
        const int n = wn * 112 + nt * 8 + (lane & 3) * 2;
        const uint32_t cb = (uint32_t)(n >> 6) * 8192u;
        const uint32_t cw = (uint32_t)(n & 63) * 2u;
        *reinterpret_cast<__nv_bfloat162*>(smem + AT_P +
            swz(cb + (uint32_t)row0 * 128u + cw)) =
            __floats2bfloat162_rn(acc[nt][0], acc[nt][1]);
        *reinterpret_cast<__nv_bfloat162*>(smem + AT_P +
            swz(cb + (uint32_t)row1 * 128u + cw)) =
            __floats2bfloat162_rn(acc[nt][2], acc[nt][3]);
    }
    CP_WAIT(0);          // V arrived
    __syncthreads();

    const float inv_a = 1.0f / (ssum[row0 * 2] + ssum[row0 * 2 + 1]);
    const float inv_b = 1.0f / (ssum[row1 * 2] + ssum[row1 * 2 + 1]);

    // ---- phase 2: O = P @ V.  warp (wm, wn): rows wm*16..+16, dims wn*32..+32
    float acc3[4][4] = {};
    #pragma unroll
    for (int kk = 0; kk < 14; kk++) {
        uint32_t af[4];
        {
            const int kv0 = kk * 16 + (mtx >> 1) * 8;
            const int row = wm * 16 + (mtx & 1) * 8 + l7;
            LDMATRIX_X4(af[0], af[1], af[2], af[3],
                        sb + AT_P + swz((uint32_t)(kv0 >> 6) * 8192u
                                        + (uint32_t)row * 128u
                                        + (uint32_t)(kv0 & 63) * 2u));
        }
        uint32_t bf[4][2];
        #pragma unroll
        for (int g2 = 0; g2 < 2; g2++) {
            const int kvrow = kk * 16 + (lane & 15);
            const int colb  = (wn * 32 + g2 * 16 + (lane >> 4) * 8) * 2;
            LDMATRIX_X4_TRANS(bf[g2 * 2][0], bf[g2 * 2][1],
                              bf[g2 * 2 + 1][0], bf[g2 * 2 + 1][1],
                              sb + AT_V + swz((uint32_t)kvrow * 128u + (uint32_t)colb));
        }
        #pragma unroll
        for (int nt = 0; nt < 4; nt++)
            MMA_BF16(acc3[nt], af, bf[nt]);
    }

    // ---- write O ----
    const size_t t_a = (size_t)b * 4096 + (size_t)(y_a * 64 + x_a);
    const size_t t_b = (size_t)b * 4096 + (size_t)(y_b * 64 + x_b);
    #pragma unroll
    for (int nt = 0; nt < 4; nt++) {
        const int col = wn * 32 + nt * 8 + (lane & 3) * 2;
        *reinterpret_cast<__nv_bfloat162*>(out + t_a * CDIM + head * 64 + col) =
            __floats2bfloat162_rn(acc3[nt][0] * inv_a, acc3[nt][1] * inv_a);
        *reinterpret_cast<__nv_bfloat162*>(out + t_b * CDIM + head * 64 + col) =
            __floats2bfloat162_rn(acc3[nt][2] * inv_b, acc3[nt][3] * inv_b);
    }
}

// ---------------------------------------------------------------------------
// GeGLU: g = gelu_exact(gate) * value   (fp32 in, bf16 out)
// ---------------------------------------------------------------------------
__global__ void geglu_kernel(const float* __restrict__ ffh, __nv_bfloat16* __restrict__ g)
{
    const int idx = blockIdx.x * blockDim.x + threadIdx.x;
    const int row = idx >> 8;
    const int col = idx & 255;
    const float gate = ffh[(size_t)row * FFN + col];
    const float val  = ffh[(size_t)row * FFN + CDIM + col];
    const float ge = 0.5f * gate * (1.0f + erff(gate * 0.70710678118654752f));
    g[idx] = __float2bfloat16(ge * val);
}

// ---------------------------------------------------------------------------
// Launch
// ---------------------------------------------------------------------------
extern "C" void kernel_launch(void* const* d_in, const int* in_sizes, int n_in,
                              void* d_out, int out_size)
{
    const float* x       = (const float*)d_in[0];
    const float* norm1_w = (const float*)d_in[1];
    const float* norm2_w = (const float*)d_in[2];
    const float* w_qkv   = (const float*)d_in[3];
    const float* w_proj  = (const float*)d_in[4];
    const float* b_proj  = (const float*)d_in[5];
    const float* ff1_w   = (const float*)d_in[6];
    const float* ff1_b   = (const float*)d_in[7];
    const float* ff2_w   = (const float*)d_in[8];
    const float* ff2_b   = (const float*)d_in[9];
    float* out = (float*)d_out;

    __nv_bfloat16 *p_h, *p_qkv, *p_attn, *p_n2, *p_g;
    __nv_bfloat16 *p_wqkvT, *p_wprojT, *p_ff1T, *p_ff2T;
    float *p_x1, *p_ffh;
    cudaGetSymbolAddress((void**)&p_h,      g_h);
    cudaGetSymbolAddress((void**)&p_qkv,    g_qkv);
    cudaGetSymbolAddress((void**)&p_attn,   g_attn);
    cudaGetSymbolAddress((void**)&p_x1,     g_x1);
    cudaGetSymbolAddress((void**)&p_n2,     g_n2);
    cudaGetSymbolAddress((void**)&p_ffh,    g_ffh);
    cudaGetSymbolAddress((void**)&p_g,      g_g);
    cudaGetSymbolAddress((void**)&p_wqkvT,  g_wqkvT);
    cudaGetSymbolAddress((void**)&p_wprojT, g_wprojT);
    cudaGetSymbolAddress((void**)&p_ff1T,   g_ff1T);
    cudaGetSymbolAddress((void**)&p_ff2T,   g_ff2T);

    cudaFuncSetAttribute(gemm_mma_kernel,
                         cudaFuncAttributeMaxDynamicSharedMemorySize, SM_SIZE);
    cudaFuncSetAttribute(attn_mma_kernel,
                         cudaFuncAttributeMaxDynamicSharedMemorySize, AT_SIZE);

    // 0. all weight transposes in one launch
    transpose_all_kernel<<<dim3(56, 8), dim3(32, 8)>>>(
        w_qkv, p_wqkvT, w_proj, p_wprojT, ff1_w, p_ff1T, ff2_w, p_ff2T);

    // 1. h = rope2d(rmsnorm(x)) -> bf16
    rmsnorm_rope_kernel<<<NTOK, 128>>>(x, norm1_w, p_h, 1);

    // 2. qkv = h @ w_qkv -> bf16
    gemm_mma_kernel<<<dim3(QKVN / 128, NTOK / 128), 256, SM_SIZE>>>(
        p_h, p_wqkvT, nullptr, nullptr, nullptr, p_qkv, QKVN, 0);

    // 3. tiled tensor-core neighborhood attention -> bf16
    attn_mma_kernel<<<dim3(64, 4, 2), 256, AT_SIZE>>>(p_qkv, p_attn);

    // 4. x1 = x + attn @ w_proj + b_proj   (fp32)
    gemm_mma_kernel<<<dim3(CDIM / 128, NTOK / 128), 256, SM_SIZE>>>(
        p_attn, p_wprojT, b_proj, x, p_x1, nullptr, CDIM, 2);

    // 5. n2 = rmsnorm(x1) -> bf16
    rmsnorm_rope_kernel<<<NTOK, 128>>>(p_x1, norm2_w, p_n2, 0);

    // 6. ffh = n2 @ ff1_w + ff1_b   (fp32)
    gemm_mma_kernel<<<dim3(FFN / 128, NTOK / 128), 256, SM_SIZE>>>(
        p_n2, p_ff1T, ff1_b, nullptr, p_ffh, nullptr, FFN, 1);

    // 7. g = gelu(gate) * value -> bf16
    geglu_kernel<<<(NTOK * CDIM) / 256, 256>>>(p_ffh, p_g);

    // 8. out = x1 + g @ ff2_w + ff2_b   (fp32)
    gemm_mma_kernel<<<dim3(CDIM / 128, NTOK / 128), 256, SM_SIZE>>>(
        p_g, p_ff2T, ff2_b, p_x1, out, nullptr, CDIM, 2);
}

// round 6
// speedup vs baseline: 4.2245x; 1.0537x over previous
#include <cuda_runtime.h>
#include <cuda_bf16.h>
#include <math.h>
#include <stdint.h>

// ---------------------------------------------------------------------------
// Problem constants (B=2, H=W=64, C=256, nh=4, hd=64, k=7)
// ---------------------------------------------------------------------------
#define NTOK   8192
#define CDIM   256
#define GK     256
#define QKVN   768
#define FFN    512
#define KS     7
#define KK     49

// ---------------------------------------------------------------------------
// Scratch (__device__ globals; allocation forbidden)
// ---------------------------------------------------------------------------
__device__ __nv_bfloat16 g_h   [NTOK * CDIM];
__device__ __nv_bfloat16 g_qkv [NTOK * QKVN];
__device__ __nv_bfloat16 g_attn[NTOK * CDIM];
__device__ float         g_x1  [NTOK * CDIM];
__device__ __nv_bfloat16 g_n2  [NTOK * CDIM];
__device__ float         g_ffh [NTOK * FFN];
__device__ __nv_bfloat16 g_g   [NTOK * CDIM];
__device__ __nv_bfloat16 g_wqkvT[QKVN * GK];
__device__ __nv_bfloat16 g_wprojT[CDIM * GK];
__device__ __nv_bfloat16 g_ff1T [FFN  * GK];
__device__ __nv_bfloat16 g_ff2T [CDIM * GK];

// ---------------------------------------------------------------------------
// PTX helpers
// ---------------------------------------------------------------------------
__device__ __forceinline__ uint32_t smem_u32(const void* p) {
    uint32_t a;
    asm("{ .reg .u64 t; cvta.to.shared.u64 t, %1; cvt.u32.u64 %0, t; }"
        : "=r"(a) : "l"(p));
    return a;
}
#define LDMATRIX_X4(r0, r1, r2, r3, a) \
    asm volatile("ldmatrix.sync.aligned.m8n8.x4.shared.b16 {%0,%1,%2,%3}, [%4];" \
                 : "=r"(r0), "=r"(r1), "=r"(r2), "=r"(r3) : "r"(a))
#define LDMATRIX_X4_TRANS(r0, r1, r2, r3, a) \
    asm volatile("ldmatrix.sync.aligned.m8n8.x4.trans.shared.b16 {%0,%1,%2,%3}, [%4];" \
                 : "=r"(r0), "=r"(r1), "=r"(r2), "=r"(r3) : "r"(a))
#define MMA_BF16(d, a, b) \
    asm volatile("mma.sync.aligned.m16n8k16.row.col.f32.bf16.bf16.f32 " \
                 "{%0,%1,%2,%3}, {%4,%5,%6,%7}, {%8,%9}, {%0,%1,%2,%3};" \
                 : "+f"((d)[0]), "+f"((d)[1]), "+f"((d)[2]), "+f"((d)[3]) \
                 : "r"((a)[0]), "r"((a)[1]), "r"((a)[2]), "r"((a)[3]), \
                   "r"((b)[0]), "r"((b)[1]))
#define CP_ASYNC16(dst, src) \
    asm volatile("cp.async.cg.shared.global [%0], [%1], 16;" :: "r"(dst), "l"(src))
#define CP_COMMIT() asm volatile("cp.async.commit_group;" ::: "memory")
#define CP_WAIT(n)  asm volatile("cp.async.wait_group %0;" :: "n"(n) : "memory")

__device__ __forceinline__ uint32_t swz(uint32_t off) { return off ^ ((off >> 3) & 0x70); }

// ---------------------------------------------------------------------------
// Fused weight convert+transpose (one launch for all 4 weights)
// ---------------------------------------------------------------------------
__global__ void transpose_all_kernel(const float* __restrict__ w0, __nv_bfloat16* __restrict__ o0,
                                     const float* __restrict__ w1, __nv_bfloat16* __restrict__ o1,
                                     const float* __restrict__ w2, __nv_bfloat16* __restrict__ o2,
                                     const float* __restrict__ w3, __nv_bfloat16* __restrict__ o3)
{
    const float* w; __nv_bfloat16* o; int N, nb;
    const int bx = blockIdx.x;
    if      (bx < 24) { w = w0; o = o0; N = QKVN; nb = bx;      }
    else if (bx < 32) { w = w1; o = o1; N = CDIM; nb = bx - 24; }
    else if (bx < 48) { w = w2; o = o2; N = FFN;  nb = bx - 32; }
    else              { w = w3; o = o3; N = CDIM; nb = bx - 48; }

    __shared__ float t[32][33];
    const int n0 = nb * 32, k0 = blockIdx.y * 32;
    const int tx = threadIdx.x, ty = threadIdx.y;
    #pragma unroll
    for (int i = 0; i < 32; i += 8)
        t[ty + i][tx] = w[(size_t)(k0 + ty + i) * N + n0 + tx];
    __syncthreads();
    #pragma unroll
    for (int i = 0; i < 32; i += 8)
        o[(size_t)(n0 + ty + i) * GK + k0 + tx] = __float2bfloat16(t[tx][ty + i]);
}

// ---------------------------------------------------------------------------
// RMSNorm (+ optional RoPE2D), fp32 in, bf16 out.
// ---------------------------------------------------------------------------
__global__ void rmsnorm_rope_kernel(const float* __restrict__ x,
                                    const float* __restrict__ w,
                                    __nv_bfloat16* __restrict__ out,
                                    int do_rope)
{
    const int t = blockIdx.x;
    const int i = threadIdx.x;
    float2 v = reinterpret_cast<const float2*>(x + (size_t)t * CDIM)[i];

    float ss = v.x * v.x + v.y * v.y;
    #pragma unroll
    for (int off = 16; off; off >>= 1)
        ss += __shfl_xor_sync(0xffffffffu, ss, off);
    __shared__ float red[4];
    if ((i & 31) == 0) red[i >> 5] = ss;
    __syncthreads();
    const float r = rsqrtf((red[0] + red[1] + red[2] + red[3]) * (1.0f / CDIM) + 1e-6f);

    const float2 wv = reinterpret_cast<const float2*>(w)[i];
    float a = v.x * r * wv.x;
    float b = v.y * r * wv.y;

    if (do_rope) {
        const int yy = (t >> 6) & 63;
        const int xx = t & 63;
        const int j  = i & 63;
        const float pos = (i < 64) ? (float)yy : (float)xx;
        const float inv = exp2f((float)j * (-13.28771237954945f / 64.0f));
        float c, s;
        sincosf(pos * inv, &s, &c);
        const float na = a * c - b * s;
        const float nb = a * s + b * c;
        a = na; b = nb;
    }
    reinterpret_cast<__nv_bfloat162*>(out + (size_t)t * CDIM)[i] =
        __floats2bfloat162_rn(a, b);
}

// ---------------------------------------------------------------------------
// mma.sync bf16 GEMM, double-buffered K-chunk ring (2 stages x 32KB = 64KB)
// -> 2 CTAs/SM. CTA 128x128, 8 warps (2M x 4N), warp tile 64x32.
// ---------------------------------------------------------------------------
#define GS_STAGE 32768            // 16KB A + 16KB B per stage
#define SM_SIZE  65536

__global__ __launch_bounds__(256, 2)
void gemm_mma_kernel(const __nv_bfloat16* __restrict__ A,
                     const __nv_bfloat16* __restrict__ Bt,
                     const float* __restrict__ bias,
                     const float* __restrict__ residual,
                     float* __restrict__ C,
                     __nv_bfloat16* __restrict__ Cb,
                     int N, int mode)
{
    extern __shared__ __align__(1024) char smem[];
    const uint32_t sb = smem_u32(smem);
    const int tid  = threadIdx.x;
    const int wid  = tid >> 5;
    const int lane = tid & 31;
    const int bm   = blockIdx.y * 128;
    const int bn   = blockIdx.x * 128;
    const int wm   = wid & 1;
    const int wn   = wid >> 1;

    const int lrow = tid >> 3;            // loader row 0..31 (x8 iters -> 128)
    const int lch  = tid & 7;             // 16B chunk in row

    // ---- load one K-chunk (64 cols) of A and B into stage buffer ----
    #define LOAD_CHUNK(kc, stage) do {                                            \
        const uint32_t s0 = (uint32_t)(stage) * GS_STAGE;                         \
        _Pragma("unroll")                                                         \
        for (int it = 0; it < 4; it++) {                                          \
            const int row = it * 32 + lrow;                                      \
            uint32_t off = swz((uint32_t)row * 128u + (uint32_t)lch * 16u);      \
            CP_ASYNC16(sb + s0 + off,                                             \
                       A  + (size_t)(bm + row) * GK + (kc) * 64 + lch * 8);      \
            CP_ASYNC16(sb + s0 + 16384u + off,                                    \
                       Bt + (size_t)(bn + row) * GK + (kc) * 64 + lch * 8);      \
        }                                                                         \
        CP_COMMIT();                                                              \
    } while (0)

    LOAD_CHUNK(0, 0);
    LOAD_CHUNK(1, 1);

    float acc[4][4][4] = {};
    const int mtx = lane >> 3;
    const int l7  = lane & 7;

    #pragma unroll
    for (int kc = 0; kc < 4; kc++) {
        if (kc < 3) CP_WAIT(1); else CP_WAIT(0);
        __syncthreads();

        const uint32_t sA = sb + (uint32_t)(kc & 1) * GS_STAGE;
        const uint32_t sB = sA + 16384u;

        #pragma unroll
        for (int s16 = 0; s16 < 4; s16++) {
            const int chunk0 = s16 * 2;

            uint32_t af[4][4];
            #pragma unroll
            for (int mt = 0; mt < 4; mt++) {
                const int row   = wm * 64 + mt * 16 + (mtx & 1) * 8 + l7;
                const int chunk = chunk0 + (mtx >> 1);
                LDMATRIX_X4(af[mt][0], af[mt][1], af[mt][2], af[mt][3],
                            sA + swz((uint32_t)row * 128u + (uint32_t)chunk * 16u));
            }
            uint32_t bf[4][2];
            #pragma unroll
            for (int pair = 0; pair < 2; pair++) {
                const int nrow  = wn * 32 + pair * 16 + (mtx >> 1) * 8 + l7;
                const int chunk = chunk0 + (mtx & 1);
                LDMATRIX_X4(bf[pair * 2][0], bf[pair * 2][1],
                            bf[pair * 2 + 1][0], bf[pair * 2 + 1][1],
                            sB + swz((uint32_t)nrow * 128u + (uint32_t)chunk * 16u));
            }
            #pragma unroll
            for (int mt = 0; mt < 4; mt++)
                #pragma unroll
                for (int nt = 0; nt < 4; nt++)
                    MMA_BF16(acc[mt][nt], af[mt], bf[nt]);
        }
        __syncthreads();
        if (kc < 2) LOAD_CHUNK(kc + 2, kc & 1);
    }

    const int rbase = bm + wm * 64 + (lane >> 2);
    const int cbase = bn + wn * 32 + (lane & 3) * 2;
    #pragma unroll
    for (int mt = 0; mt < 4; mt++) {
        #pragma unroll
        for (int half = 0; half < 2; half++) {
            const int row = rbase + mt * 16 + half * 8;
            #pragma unroll
            for (int nt = 0; nt < 4; nt++) {
                const int col = cbase + nt * 8;
                float ox = acc[mt][nt][half * 2];
                float oy = acc[mt][nt][half * 2 + 1];
                const size_t idx = (size_t)row * N + col;
                if (mode == 0) {
                    *reinterpret_cast<__nv_bfloat162*>(&Cb[idx]) =
                        __floats2bfloat162_rn(ox, oy);
                } else {
                    ox += bias[col];
                    oy += bias[col + 1];
                    if (mode == 2) {
                        const float2 rr = *reinterpret_cast<const float2*>(&residual[idx]);
                        ox += rr.x; oy += rr.y;
                    }
                    *reinterpret_cast<float2*>(&C[idx]) = make_float2(ox, oy);
                }
            }
        }
    }
}

// ---------------------------------------------------------------------------
// Tiled tensor-core neighborhood attention (register-dieted, 2 CTAs/SM).
// One CTA per (8x8 token tile, head, batch). 256 threads (8 warps).
// ---------------------------------------------------------------------------
#define AT_Q    0
#define AT_K    8192
#define AT_V    36864
#define AT_P    65536
#define AT_MAX  98304
#define AT_SUM  98816
#define AT_SIZE 99328

__global__ __launch_bounds__(256, 2)
void attn_mma_kernel(const __nv_bfloat16* __restrict__ qkv,
                     __nv_bfloat16* __restrict__ out)
{
    extern __shared__ __align__(1024) char smem[];
    const uint32_t sb = smem_u32(smem);
    float* smax = reinterpret_cast<float*>(smem + AT_MAX);   // [64][2]
    float* ssum = reinterpret_cast<float*>(smem + AT_SUM);   // [64][2]

    const int tid  = threadIdx.x;
    const int wid  = tid >> 5;
    const int lane = tid & 31;
    const int head = blockIdx.y;
    const int b    = blockIdx.z;
    const int ty0  = (blockIdx.x >> 3) * 8;
    const int tx0  = (blockIdx.x & 7) * 8;
    const int ny0  = min(max(ty0 - 3, 0), 50);
    const int nx0  = min(max(tx0 - 3, 0), 50);

    const __nv_bfloat16* base = qkv + (size_t)b * 4096 * QKVN + head * 64;

    // ---- async loads: Q, then K, then V (separate commit groups) ----
    #pragma unroll
    for (int i = 0; i < 2; i++) {
        const int idx = i * 256 + tid;
        const int m = idx >> 3, ch = idx & 7;
        const int y = ty0 + (m >> 3), x = tx0 + (m & 7);
        uint32_t off = swz((uint32_t)m * 128u + (uint32_t)ch * 16u);
        CP_ASYNC16(sb + AT_Q + off, base + (size_t)(y * 64 + x) * QKVN + ch * 8);
    }
    CP_COMMIT();
    #pragma unroll
    for (int i = 0; i < 7; i++) {
        const int idx = i * 256 + tid;
        const int kv = idx >> 3, ch = idx & 7;
        const int r = kv >> 4, c = kv & 15;
        uint32_t off = swz((uint32_t)kv * 128u + (uint32_t)ch * 16u);
        if (c < 14)
            CP_ASYNC16(sb + AT_K + off,
                       base + (size_t)((ny0 + r) * 64 + nx0 + c) * QKVN + CDIM + ch * 8);
        else
            *reinterpret_cast<uint4*>(smem + AT_K + off) = make_uint4(0, 0, 0, 0);
    }
    CP_COMMIT();
    #pragma unroll
    for (int i = 0; i < 7; i++) {
        const int idx = i * 256 + tid;
        const int kv = idx >> 3, ch = idx & 7;
        const int r = kv >> 4, c = kv & 15;
        uint32_t off = swz((uint32_t)kv * 128u + (uint32_t)ch * 16u);
        if (c < 14)
            CP_ASYNC16(sb + AT_V + off,
                       base + (size_t)((ny0 + r) * 64 + nx0 + c) * QKVN + 2 * CDIM + ch * 8);
        else
            *reinterpret_cast<uint4*>(smem + AT_V + off) = make_uint4(0, 0, 0, 0);
    }
    CP_COMMIT();

    const int wm  = wid & 3;
    const int wn  = wid >> 2;
    const int mtx = lane >> 3;
    const int l7  = lane & 7;

    CP_WAIT(1);
    __syncthreads();

    // ---- phase 1: S = Q @ K^T. Q fragments cached across k; B tiles in
    //      groups of 8+6 to cap register liveness. ----
    uint32_t af[4][4];
    #pragma unroll
    for (int k16 = 0; k16 < 4; k16++) {
        const int row   = wm * 16 + (mtx & 1) * 8 + l7;
        const int chunk = k16 * 2 + (mtx >> 1);
        LDMATRIX_X4(af[k16][0], af[k16][1], af[k16][2], af[k16][3],
                    sb + AT_Q + swz((uint32_t)row * 128u + (uint32_t)chunk * 16u));
    }

    float acc[14][4] = {};
    #pragma unroll
    for (int k16 = 0; k16 < 4; k16++) {
        #pragma unroll
        for (int grp = 0; grp < 2; grp++) {
            const int nt0    = grp * 8;               // tiles 0..7 then 8..13
            const int npairs = grp ? 3 : 4;
            uint32_t bf[8][2];
            #pragma unroll
            for (int pair = 0; pair < 4; pair++) {
                if (pair < npairs) {
                    const int nrow  = wn * 112 + (nt0 + pair * 2) * 8 + (mtx >> 1) * 8 + l7;
                    const int chunk = k16 * 2 + (mtx & 1);
                    LDMATRIX_X4(bf[pair * 2][0], bf[pair * 2][1],
                                bf[pair * 2 + 1][0], bf[pair * 2 + 1][1],
                                sb + AT_K + swz((uint32_t)nrow * 128u + (uint32_t)chunk * 16u));
                }
            }
            const int ntiles = grp ? 6 : 8;
            #pragma unroll
            for (int j = 0; j < 8; j++)
                if (j < ntiles)
                    MMA_BF16(acc[nt0 + j], af[k16], bf[j]);
        }
    }

    // ---- masks (7x7 window per token) ----
    const int row0 = wm * 16 + (lane >> 2);
    const int row1 = row0 + 8;
    const int y_a = ty0 + (row0 >> 3), x_a = tx0 + (row0 & 7);
    const int y_b = ty0 + (row1 >> 3), x_b = tx0 + (row1 & 7);
    const int rlo_a = min(max(y_a - 3, 0), 57) - ny0;
    const int clo_a = min(max(x_a - 3, 0), 57) - nx0;
    const int rlo_b = min(max(y_b - 3, 0), 57) - ny0;
    const int clo_b = min(max(x_b - 3, 0), 57) - nx0;

    uint32_t vm_a = 0, vm_b = 0;
    #pragma unroll
    for (int nt = 0; nt < 14; nt++) {
        #pragma unroll
        for (int j = 0; j < 2; j++) {
            const int n = wn * 112 + nt * 8 + (lane & 3) * 2 + j;
            const int r = n >> 4, c = n & 15;
            if (c < 14 && (unsigned)(r - rlo_a) < 7u && (unsigned)(c - clo_a) < 7u)
                vm_a |= 1u << (nt * 2 + j);
            if (c < 14 && (unsigned)(r - rlo_b) < 7u && (unsigned)(c - clo_b) < 7u)
                vm_b |= 1u << (nt * 2 + j);
        }
    }

    // ---- row max ----
    float mx_a = -3e38f, mx_b = -3e38f;
    #pragma unroll
    for (int nt = 0; nt < 14; nt++) {
        #pragma unroll
        for (int j = 0; j < 2; j++) {
            if (vm_a & (1u << (nt * 2 + j))) mx_a = fmaxf(mx_a, acc[nt][j]);
            if (vm_b & (1u << (nt * 2 + j))) mx_b = fmaxf(mx_b, acc[nt][2 + j]);
        }
    }
    mx_a = fmaxf(mx_a, __shfl_xor_sync(0xffffffffu, mx_a, 1));
    mx_a = fmaxf(mx_a, __shfl_xor_sync(0xffffffffu, mx_a, 2));
    mx_b = fmaxf(mx_b, __shfl_xor_sync(0xffffffffu, mx_b, 1));
    mx_b = fmaxf(mx_b, __shfl_xor_sync(0xffffffffu, mx_b, 2));
    if ((lane & 3) == 0) {
        smax[row0 * 2 + wn] = mx_a;
        smax[row1 * 2 + wn] = mx_b;
    }
    __syncthreads();
    const float M_a = fmaxf(smax[row0 * 2], smax[row0 * 2 + 1]);
    const float M_b = fmaxf(smax[row1 * 2], smax[row1 * 2 + 1]);

    // ---- exp + row sum ----
    const float SC = 0.18033688011112042f;   // 0.125 * log2(e)
    float sm_a = 0.0f, sm_b = 0.0f;
    #pragma unroll
    for (int nt = 0; nt < 14; nt++) {
        #pragma unroll
        for (int j = 0; j < 2; j++) {
            float ea = (vm_a & (1u << (nt * 2 + j)))
                     ? exp2f((acc[nt][j] - M_a) * SC) : 0.0f;
            float eb = (vm_b & (1u << (nt * 2 + j)))
                     ? exp2f((acc[nt][2 + j] - M_b) * SC) : 0.0f;
            acc[nt][j] = ea; acc[nt][2 + j] = eb;
            sm_a += ea; sm_b += eb;
        }
    }
    sm_a += __shfl_xor_sync(0xffffffffu, sm_a, 1);
    sm_a += __shfl_xor_sync(0xffffffffu, sm_a, 2);
    sm_b += __shfl_xor_sync(0xffffffffu, sm_b, 1);
    sm_b += __shfl_xor_sync(0xffffffffu, sm_b, 2);
    if ((lane & 3) == 0) {
        ssum[row0 * 2 + wn] = sm_a;
        ssum[row1 * 2 + wn] = sm_b;
    }

    // ---- store P (bf16, swizzled, 4 col-blocks of 64 kv) ----
    #pragma unroll
    for (int nt = 0; nt < 14; nt++) {
        const int n = wn * 112 + nt * 8 + (lane & 3) * 2;
        const uint32_t cb = (uint32_t)(n >> 6) * 8192u;
        const uint32_t cw = (uint32_t)(n & 63) * 2u;
        *reinterpret_cast<__nv_bfloat162*>(smem + AT_P +
            swz(cb + (uint32_t)row0 * 128u + cw)) =
            __floats2bfloat162_rn(acc[nt][0], acc[nt][1]);
        *reinterpret_cast<__nv_bfloat162*>(smem + AT_P +
            swz(cb + (uint32_t)row1 * 128u + cw)) =
            __floats2bfloat162_rn(acc[nt][2], acc[nt][3]);
    }
    CP_WAIT(0);
    __syncthreads();

    const float inv_a = 1.0f / (ssum[row0 * 2] + ssum[row0 * 2 + 1]);
    const float inv_b = 1.0f / (ssum[row1 * 2] + ssum[row1 * 2 + 1]);

    // ---- phase 2: O = P @ V ----
    float acc3[4][4] = {};
    #pragma unroll
    for (int kk = 0; kk < 14; kk++) {
        uint32_t pf[4];
        {
            const int kv0 = kk * 16 + (mtx >> 1) * 8;
            const int row = wm * 16 + (mtx & 1) * 8 + l7;
            LDMATRIX_X4(pf[0], pf[1], pf[2], pf[3],
                        sb + AT_P + swz((uint32_t)(kv0 >> 6) * 8192u
                                        + (uint32_t)row * 128u
                                        + (uint32_t)(kv0 & 63) * 2u));
        }
        uint32_t vf[4][2];
        #pragma unroll
        for (int g2 = 0; g2 < 2; g2++) {
            const int kvrow = kk * 16 + (lane & 15);
            const int colb  = (wn * 32 + g2 * 16 + (lane >> 4) * 8) * 2;
            LDMATRIX_X4_TRANS(vf[g2 * 2][0], vf[g2 * 2][1],
                              vf[g2 * 2 + 1][0], vf[g2 * 2 + 1][1],
                              sb + AT_V + swz((uint32_t)kvrow * 128u + (uint32_t)colb));
        }
        #pragma unroll
        for (int nt = 0; nt < 4; nt++)
            MMA_BF16(acc3[nt], pf, vf[nt]);
    }

    // ---- write O ----
    const size_t t_a = (size_t)b * 4096 + (size_t)(y_a * 64 + x_a);
    const size_t t_b = (size_t)b * 4096 + (size_t)(y_b * 64 + x_b);
    #pragma unroll
    for (int nt = 0; nt < 4; nt++) {
        const int col = wn * 32 + nt * 8 + (lane & 3) * 2;
        *reinterpret_cast<__nv_bfloat162*>(out + t_a * CDIM + head * 64 + col) =
            __floats2bfloat162_rn(acc3[nt][0] * inv_a, acc3[nt][1] * inv_a);
        *reinterpret_cast<__nv_bfloat162*>(out + t_b * CDIM + head * 64 + col) =
            __floats2bfloat162_rn(acc3[nt][2] * inv_b, acc3[nt][3] * inv_b);
    }
}

// ---------------------------------------------------------------------------
// GeGLU: g = gelu_exact(gate) * value   (fp32 in, bf16 out)
// ---------------------------------------------------------------------------
__global__ void geglu_kernel(const float* __restrict__ ffh, __nv_bfloat16* __restrict__ g)
{
    const int idx = blockIdx.x * blockDim.x + threadIdx.x;
    const int row = idx >> 8;
    const int col = idx & 255;
    const float gate = ffh[(size_t)row * FFN + col];
    const float val  = ffh[(size_t)row * FFN + CDIM + col];
    const float ge = 0.5f * gate * (1.0f + erff(gate * 0.70710678118654752f));
    g[idx] = __float2bfloat16(ge * val);
}

// ---------------------------------------------------------------------------
// Launch
// ---------------------------------------------------------------------------
extern "C" void kernel_launch(void* const* d_in, const int* in_sizes, int n_in,
                              void* d_out, int out_size)
{
    const float* x       = (const float*)d_in[0];
    const float* norm1_w = (const float*)d_in[1];
    const float* norm2_w = (const float*)d_in[2];
    const float* w_qkv   = (const float*)d_in[3];
    const float* w_proj  = (const float*)d_in[4];
    const float* b_proj  = (const float*)d_in[5];
    const float* ff1_w   = (const float*)d_in[6];
    const float* ff1_b   = (const float*)d_in[7];
    const float* ff2_w   = (const float*)d_in[8];
    const float* ff2_b   = (const float*)d_in[9];
    float* out = (float*)d_out;

    __nv_bfloat16 *p_h, *p_qkv, *p_attn, *p_n2, *p_g;
    __nv_bfloat16 *p_wqkvT, *p_wprojT, *p_ff1T, *p_ff2T;
    float *p_x1, *p_ffh;
    cudaGetSymbolAddress((void**)&p_h,      g_h);
    cudaGetSymbolAddress((void**)&p_qkv,    g_qkv);
    cudaGetSymbolAddress((void**)&p_attn,   g_attn);
    cudaGetSymbolAddress((void**)&p_x1,     g_x1);
    cudaGetSymbolAddress((void**)&p_n2,     g_n2);
    cudaGetSymbolAddress((void**)&p_ffh,    g_ffh);
    cudaGetSymbolAddress((void**)&p_g,      g_g);
    cudaGetSymbolAddress((void**)&p_wqkvT,  g_wqkvT);
    cudaGetSymbolAddress((void**)&p_wprojT, g_wprojT);
    cudaGetSymbolAddress((void**)&p_ff1T,   g_ff1T);
    cudaGetSymbolAddress((void**)&p_ff2T,   g_ff2T);

    cudaFuncSetAttribute(gemm_mma_kernel,
                         cudaFuncAttributeMaxDynamicSharedMemorySize, SM_SIZE);
    cudaFuncSetAttribute(attn_mma_kernel,
                         cudaFuncAttributeMaxDynamicSharedMemorySize, AT_SIZE);

    // 0. all weight transposes in one launch
    transpose_all_kernel<<<dim3(56, 8), dim3(32, 8)>>>(
        w_qkv, p_wqkvT, w_proj, p_wprojT, ff1_w, p_ff1T, ff2_w, p_ff2T);

    // 1. h = rope2d(rmsnorm(x)) -> bf16
    rmsnorm_rope_kernel<<<NTOK, 128>>>(x, norm1_w, p_h, 1);

    // 2. qkv = h @ w_qkv -> bf16
    gemm_mma_kernel<<<dim3(QKVN / 128, NTOK / 128), 256, SM_SIZE>>>(
        p_h, p_wqkvT, nullptr, nullptr, nullptr, p_qkv, QKVN, 0);

    // 3. tiled tensor-core neighborhood attention -> bf16
    attn_mma_kernel<<<dim3(64, 4, 2), 256, AT_SIZE>>>(p_qkv, p_attn);

    // 4. x1 = x + attn @ w_proj + b_proj   (fp32)
    gemm_mma_kernel<<<dim3(CDIM / 128, NTOK / 128), 256, SM_SIZE>>>(
        p_attn, p_wprojT, b_proj, x, p_x1, nullptr, CDIM, 2);

    // 5. n2 = rmsnorm(x1) -> bf16
    rmsnorm_rope_kernel<<<NTOK, 128>>>(p_x1, norm2_w, p_n2, 0);

    // 6. ffh = n2 @ ff1_w + ff1_b   (fp32)
    gemm_mma_kernel<<<dim3(FFN / 128, NTOK / 128), 256, SM_SIZE>>>(
        p_n2, p_ff1T, ff1_b, nullptr, p_ffh, nullptr, FFN, 1);

    // 7. g = gelu(gate) * value -> bf16
    geglu_kernel<<<(NTOK * CDIM) / 256, 256>>>(p_ffh, p_g);

    // 8. out = x1 + g @ ff2_w + ff2_b   (fp32)
    gemm_mma_kernel<<<dim3(CDIM / 128, NTOK / 128), 256, SM_SIZE>>>(
        p_g, p_ff2T, ff2_b, p_x1, out, nullptr, CDIM, 2);
}